// round 9
// baseline (speedup 1.0000x reference)
#include <cuda_runtime.h>
#include <math.h>
#include <limits.h>

#define S_STAGES 3
#define BATCH    32
#define NPRIOR   2000
#define LANES    4
#define DFEAT    78          // 2 + 4 + 72
#define NOFF     72
#define SB       96
#define IMG_W_F  800.0f
#define IMG_W1_F 799.0f
#define TILE     128
#define NTILE    16          // 15 full tiles + one of 80
#define RPA      44          // buffer row stride (floats), conflict-free LDS.128
#define NCAND    (NTILE * 4) // 64 candidates per column
#define NMATCH   (2 * SB * LANES)   // 768
#define NTASK    (2 * SB)           // 192
#define FIXSCALE 1099511627776.0f   // 2^40

// Scratch (device globals — no allocation allowed)
// g_cls_acc is zero at load; final_kernel re-zeroes after consuming (replay-safe).
__device__ unsigned long long g_cls_acc[2 * NPRIOR];
__device__ float g_cv[NTASK * LANES * NCAND];
__device__ int   g_ci[NTASK * LANES * NCAND];
__device__ int   g_rows[NMATCH];
__device__ float g_reg [NMATCH];
__device__ float g_iou [NMATCH];
__device__ float g_corr[NMATCH];

__device__ __forceinline__ void cp_async8(unsigned s, const void* g) {
    asm volatile("cp.async.ca.shared.global [%0], [%1], 8;\n" :: "r"(s), "l"(g));
}
__device__ __forceinline__ void cp_commit() {
    asm volatile("cp.async.commit_group;\n" ::: "memory");
}
__device__ __forceinline__ void cp_wait1() {
    asm volatile("cp.async.wait_group 1;\n" ::: "memory");
}
__device__ __forceinline__ void cp_wait0() {
    asm volatile("cp.async.wait_group 0;\n" ::: "memory");
}

// ---------------------------------------------------------------------------
// Kernel 1: dual-buffer front-loaded staging. Both phases' cp.asyncs issued
// at kernel start (2 commit groups); compute A overlaps B's in-flight loads.
// grid (96, NTILE, 2), 128 threads.
// ---------------------------------------------------------------------------
__global__ __launch_bounds__(TILE) void cost_kernel(
    const float* __restrict__ predA,
    const float* __restrict__ predB,
    const float* __restrict__ gt)
{
    const int sb     = blockIdx.x;
    const int tile   = blockIdx.y;
    const int branch = blockIdx.z;
    const int n0     = tile * TILE;
    const int T      = (n0 + TILE <= NPRIOR) ? TILE : (NPRIOR - n0);
    const float* __restrict__ pred = branch ? predB : predA;
    const int b = sb % BATCH;
    const char* gbase = (const char*)(pred + ((size_t)sb * NPRIOR + n0) * DFEAT);
    const size_t bs = (size_t)branch * SB + sb;

    __shared__ __align__(16) float sh_bufA[TILE * RPA];    // dims 0..39  (22528 B)
    __shared__ __align__(16) float sh_bufB[TILE * RPA];    // dims 40..77 (22528 B)
    __shared__ __align__(16) float sh_goff[LANES][80];
    __shared__ float sh_geo[LANES][4];
    __shared__ float sh_c[LANES][TILE];

    const int tid  = threadIdx.x;
    const int warp = tid >> 5, lane = tid & 31;
    const unsigned FULL = 0xffffffffu;
    const unsigned spA = (unsigned)__cvta_generic_to_shared(sh_bufA);
    const unsigned spB = (unsigned)__cvta_generic_to_shared(sh_bufB);

    // ---- stage A: dims 0..39 (20 x 8B per row), group 0
    {
        int row = tid / 20, c2 = tid - row * 20, f = tid;
        const int total = T * 20;
        while (f < total) {
            cp_async8(spA + (unsigned)(row * (RPA * 4) + c2 * 8),
                      gbase + (size_t)row * 312 + c2 * 8);
            f += 128; row += 6; c2 += 8;
            if (c2 >= 20) { c2 -= 20; row += 1; }
        }
        cp_commit();
    }
    // ---- stage B: dims 40..77 (19 x 8B per row), group 1 — issued immediately
    {
        int row = tid / 19, c2 = tid - row * 19, f = tid;
        const int total = T * 19;
        while (f < total) {
            cp_async8(spB + (unsigned)(row * (RPA * 4) + c2 * 8),
                      gbase + (size_t)row * 312 + 160 + c2 * 8);
            f += 128; row += 6; c2 += 14;
            if (c2 >= 19) { c2 -= 19; row += 1; }
        }
        cp_commit();
    }

    // gt tables + B-buffer zero pads (overlap with async loads)
    for (int i = tid; i < LANES * 80; i += TILE) {
        int l = i / 80, d = i % 80;
        float v = 0.0f;
        if (d >= 6 && d < DFEAT)
            v = gt[((size_t)b * LANES + l) * DFEAT + d] * (1.0f / IMG_W1_F);
        sh_goff[l][d] = v;
    }
    if (tid < 16)
        sh_geo[tid >> 2][tid & 3] =
            gt[((size_t)b * LANES + (tid >> 2)) * DFEAT + 2 + (tid & 3)];
    if (tid < T) {
        sh_bufB[tid * RPA + 38] = 0.0f;   // dims 78,79 equivalent
        sh_bufB[tid * RPA + 39] = 0.0f;
    }

    cp_wait1();          // group 0 (A) complete for this thread
    __syncthreads();     // A visible block-wide; B still in flight

    // ---- compute phase A: dims 0..39
    float cg[LANES], o[LANES];
    float score = 0.0f;
    if (tid < T) {
        const float* rp = sh_bufA + tid * RPA;
        float4 p0 = *reinterpret_cast<const float4*>(rp);
        float4 p1 = *reinterpret_cast<const float4*>(rp + 4);
        #pragma unroll
        for (int l = 0; l < LANES; l++) {
            cg[l] = fabsf(p0.z - sh_geo[l][0]) + fabsf(p0.w - sh_geo[l][1])
                  + fabsf(p1.x - sh_geo[l][2]) + fabsf(p1.y - sh_geo[l][3]);
            o[l]  = fabsf(p1.z - sh_goff[l][6]) + fabsf(p1.w - sh_goff[l][7]);
        }
        #pragma unroll
        for (int c = 2; c < 10; c++) {
            float4 pv = *reinterpret_cast<const float4*>(rp + 4 * c);
            #pragma unroll
            for (int l = 0; l < LANES; l++) {
                float4 gv = *reinterpret_cast<const float4*>(&sh_goff[l][4 * c]);
                o[l] += fabsf(pv.x - gv.x) + fabsf(pv.y - gv.y)
                      + fabsf(pv.z - gv.z) + fabsf(pv.w - gv.w);
            }
        }
        float x0 = p0.x, x1 = p0.y;
        float m  = fmaxf(x0, x1);
        float e0 = expf(x0 - m), e1 = expf(x1 - m);
        float denom = e0 + e1;
        score = e1 / denom;
        float lse = m + logf(denom);
        float om0 = 1.0f - e0 / denom;
        float cneg = -0.1f * om0 * om0 * (x0 - lse);
        atomicAdd(&g_cls_acc[branch * NPRIOR + n0 + tid],
                  (unsigned long long)(long long)__float2ll_rn(cneg * FIXSCALE));
    }

    cp_wait0();          // group 1 (B) complete
    __syncthreads();

    // ---- compute phase B: dims 40..77 (cols 38,39 zero-padded)
    if (tid < T) {
        const float* rp = sh_bufB + tid * RPA;
        #pragma unroll
        for (int c = 0; c < 10; c++) {
            float4 pv = *reinterpret_cast<const float4*>(rp + 4 * c);
            #pragma unroll
            for (int l = 0; l < LANES; l++) {
                float4 gv = *reinterpret_cast<const float4*>(&sh_goff[l][40 + 4 * c]);
                o[l] += fabsf(pv.x - gv.x) + fabsf(pv.y - gv.y)
                      + fabsf(pv.z - gv.z) + fabsf(pv.w - gv.w);
            }
        }
        #pragma unroll
        for (int l = 0; l < LANES; l++)
            sh_c[l][tid] = cg[l] + o[l] * (1.0f / 72.0f) - score;
    } else {
        #pragma unroll
        for (int l = 0; l < LANES; l++) sh_c[l][tid] = INFINITY;
    }
    __syncthreads();

    // ---- warp w: top-4 of column w within tile, first-index tie-break
    {
        const int w = warp;
        const size_t base = ((bs * LANES + w) * NTILE + tile) * 4;
        #pragma unroll
        for (int pass = 0; pass < 4; pass++) {
            float v = INFINITY; int li = INT_MAX;
            #pragma unroll
            for (int j0 = 0; j0 < TILE; j0 += 32) {
                int j = j0 + lane;
                float cc = sh_c[w][j];
                if (cc < v || (cc == v && j < li)) { v = cc; li = j; }
            }
            #pragma unroll
            for (int off = 16; off; off >>= 1) {
                float v2 = __shfl_xor_sync(FULL, v, off);
                int   i2 = __shfl_xor_sync(FULL, li, off);
                if (v2 < v || (v2 == v && i2 < li)) { v = v2; li = i2; }
            }
            if (lane == 0) {
                g_cv[base + pass] = v;
                g_ci[base + pass] = n0 + li;
                sh_c[w][li] = INFINITY;
            }
            __syncwarp(FULL);
        }
    }
}

// ---------------------------------------------------------------------------
// Kernel 2: per-task greedy merge + reg/iou/corr. grid 192, 128 threads.
// ---------------------------------------------------------------------------
__global__ __launch_bounds__(128) void match_kernel(
    const float* __restrict__ predA,
    const float* __restrict__ predB,
    const float* __restrict__ gt)
{
    const int task   = blockIdx.x;             // 0..191
    const int branch = task / SB;
    const int sb     = task % SB;
    const int b      = sb % BATCH;

    __shared__ int rows_sh[LANES];

    const int tid  = threadIdx.x;
    const int warp = tid >> 5, lane = tid & 31;
    const unsigned FULL = 0xffffffffu;

    if (warp == 0) {
        const size_t base = (size_t)task * LANES * NCAND;
        float cv[LANES][2]; int ci[LANES][2];
        #pragma unroll
        for (int col = 0; col < LANES; col++) {
            cv[col][0] = g_cv[base + col * NCAND + lane];
            cv[col][1] = g_cv[base + col * NCAND + 32 + lane];
            ci[col][0] = g_ci[base + col * NCAND + lane];
            ci[col][1] = g_ci[base + col * NCAND + 32 + lane];
        }
        int u0 = -1, u1 = -1, u2 = -1;
        #pragma unroll
        for (int col = 0; col < LANES; col++) {
            float v = INFINITY; int li = INT_MAX;
            #pragma unroll
            for (int k = 0; k < 2; k++) {
                int   i2 = ci[col][k];
                float v2 = cv[col][k];
                bool excl = (i2 == u0) | (i2 == u1) | (i2 == u2);
                if (!excl && (v2 < v || (v2 == v && i2 < li))) { v = v2; li = i2; }
            }
            #pragma unroll
            for (int off = 16; off; off >>= 1) {
                float v2 = __shfl_xor_sync(FULL, v, off);
                int   i2 = __shfl_xor_sync(FULL, li, off);
                if (v2 < v || (v2 == v && i2 < li)) { v = v2; li = i2; }
            }
            if (lane == 0) { rows_sh[col] = li; g_rows[task * LANES + col] = li; }
            if (col == 0) u0 = li; else if (col == 1) u1 = li; else if (col == 2) u2 = li;
        }
    }
    __syncthreads();

    {
        const int l = warp;
        const int r = rows_sh[l];
        const int mm = task * LANES + l;
        const float* p  = (branch ? predB : predA)
                          + ((size_t)sb * NPRIOR + r) * DFEAT;
        const float* tg = gt + ((size_t)b * LANES + l) * DFEAT;

        float ovrS = 0.0f, uniS = 0.0f;
        #pragma unroll
        for (int kb = 0; kb < 3; kb++) {
            int k = kb * 32 + lane;
            if (k < NOFF) {
                float rp = p[6 + k] * IMG_W1_F;
                float rt = tg[6 + k];
                bool invalid = (rt < 0.0f) || (rt >= IMG_W_F);
                float mn = fminf(rp, rt), mx = fmaxf(rp, rt);
                if (!invalid) {
                    ovrS += (mn - mx + 30.0f);
                    uniS += (mx - mn + 30.0f);
                }
            }
        }
        #pragma unroll
        for (int off = 16; off; off >>= 1) {
            ovrS += __shfl_xor_sync(FULL, ovrS, off);
            uniS += __shfl_xor_sync(FULL, uniS, off);
        }
        if (lane == 0) {
            float iou = ovrS / (uniS + 1e-9f);
            g_iou[mm] = (1.0f - iou) * 0.25f;
            const float sc[4] = {71.0f, IMG_W1_F, 180.0f, 71.0f};
            float ssum = 0.0f;
            #pragma unroll
            for (int j = 0; j < 4; j++) {
                float d  = (p[2 + j] - tg[2 + j]) * sc[j];
                float ad = fabsf(d);
                ssum += (ad < 1.0f) ? 0.5f * d * d : ad - 0.5f;
            }
            g_reg[mm] = ssum * 0.0625f;   // mean over 4, /L

            float x0 = p[0], x1 = p[1];
            float m2  = fmaxf(x0, x1);
            float e0 = expf(x0 - m2), e1 = expf(x1 - m2);
            float denom = e0 + e1;
            float lse = m2 + logf(denom);
            float om0 = 1.0f - e0 / denom, om1 = 1.0f - e1 / denom;
            float cneg = -0.1f * om0 * om0 * (x0 - lse);
            float cpos = -0.9f * om1 * om1 * (x1 - lse);
            g_corr[mm] = (cpos - cneg) * (2.0f / 96.0f);
        }
    }
}

// ---------------------------------------------------------------------------
// Kernel 3: inst build + corrections + dual-rank radix median + weighted sum.
// Single block, 1024 threads.
// ---------------------------------------------------------------------------
__global__ __launch_bounds__(1024) void final_kernel(
    const float* __restrict__ diff,
    float* __restrict__ out)
{
    __shared__ float instA[NPRIOR];
    __shared__ float instB[NPRIOR];
    __shared__ unsigned ukey[NPRIOR];
    __shared__ int   hist[2][256];
    __shared__ float red[1024];
    __shared__ int   s_bin[2], s_k[2];

    const int tid = threadIdx.x;
    const int warp = tid >> 5, lane = tid & 31;
    const unsigned FULL = 0xffffffffu;

    const float CLS_K = (float)(2.0 / 96.0 / 1099511627776.0);
    for (int n = tid; n < NPRIOR; n += 1024) {
        long long a0 = (long long)g_cls_acc[n];
        long long b0 = (long long)g_cls_acc[NPRIOR + n];
        instA[n] = (float)a0 * CLS_K;
        instB[n] = (float)b0 * CLS_K;
        g_cls_acc[n] = 0ull;
        g_cls_acc[NPRIOR + n] = 0ull;
    }
    __syncthreads();

    if (tid < NMATCH) {
        const int branch = tid / (SB * LANES);
        const int r = g_rows[tid];
        atomicAdd(branch == 0 ? &instA[r] : &instB[r], g_corr[tid]);
    }
    if (tid >= 1016) {
        const int t = tid - 1016;
        const int branch = t >> 2, l = t & 3;
        float rs = 0.0f, is = 0.0f;
        #pragma unroll 8
        for (int i = 0; i < SB; i++) {
            rs += g_reg[(branch * SB + i) * LANES + l];
            is += g_iou[(branch * SB + i) * LANES + l];
        }
        float add = rs * (0.5f / 96.0f) + is * (2.0f / 96.0f);
        int r = g_rows[(branch * SB + (SB - 1)) * LANES + l];
        atomicAdd(branch == 0 ? &instA[r] : &instB[r], add);
    }
    __syncthreads();

    for (int n = tid; n < NPRIOR; n += 1024) {
        float f = instA[n] - instB[n];
        unsigned x = __float_as_uint(f);
        ukey[n] = (x & 0x80000000u) ? ~x : (x | 0x80000000u);
    }
    __syncthreads();

    unsigned prefix[2] = {0u, 0u};
    unsigned mask = 0u;
    int kk[2] = {999, 1000};
    for (int shift = 24; shift >= 0; shift -= 8) {
        if (tid < 512) hist[tid >> 8][tid & 255] = 0;
        __syncthreads();
        for (int n = tid; n < NPRIOR; n += 1024) {
            unsigned u = ukey[n];
            unsigned bin = (u >> shift) & 255u;
            unsigned hi = u & mask;
            if (hi == prefix[0]) atomicAdd(&hist[0][bin], 1);
            if (hi == prefix[1]) atomicAdd(&hist[1][bin], 1);
        }
        __syncthreads();
        if (tid < 64) {
            const int trk = warp;
            int kt = kk[trk];
            int cnt[8]; int local = 0;
            #pragma unroll
            for (int k2 = 0; k2 < 8; k2++) { cnt[k2] = hist[trk][lane * 8 + k2]; local += cnt[k2]; }
            int pre = local;
            #pragma unroll
            for (int off = 1; off < 32; off <<= 1) {
                int t2 = __shfl_up_sync(FULL, pre, off);
                if (lane >= off) pre += t2;
            }
            int run = pre - local;
            int foundk = -1, myrun = 0;
            #pragma unroll
            for (int k2 = 0; k2 < 8; k2++) {
                if (foundk < 0 && kt >= run && kt < run + cnt[k2]) { foundk = k2; myrun = run; }
                run += cnt[k2];
            }
            unsigned bm = __ballot_sync(FULL, foundk >= 0);
            int src = __ffs(bm) - 1;
            if (lane == src) { s_bin[trk] = lane * 8 + foundk; s_k[trk] = kt - myrun; }
        }
        __syncthreads();
        prefix[0] |= ((unsigned)s_bin[0]) << shift;
        prefix[1] |= ((unsigned)s_bin[1]) << shift;
        mask |= 0xFFu << shift;
        kk[0] = s_k[0]; kk[1] = s_k[1];
        __syncthreads();
    }
    float m0 = (prefix[0] & 0x80000000u) ? __uint_as_float(prefix[0] ^ 0x80000000u)
                                         : __uint_as_float(~prefix[0]);
    float m1 = (prefix[1] & 0x80000000u) ? __uint_as_float(prefix[1] ^ 0x80000000u)
                                         : __uint_as_float(~prefix[1]);
    float delta = 0.5f * (m0 + m1);

    float acc = 0.0f;
    for (int n = tid; n < NPRIOR; n += 1024) {
        float dm = (diff[n] + diff[NPRIOR + n] + diff[2 * NPRIOR + n]) * (1.0f / 3.0f);
        acc += (1.0f - dm) * (instA[n] - 0.5f * delta)
             + dm          * (instB[n] + 0.5f * delta);
    }
    red[tid] = acc;
    __syncthreads();
    for (int off = 512; off; off >>= 1) {
        if (tid < off) red[tid] += red[tid + off];
        __syncthreads();
    }
    if (tid == 0) out[0] = red[0];
}

// ---------------------------------------------------------------------------
extern "C" void kernel_launch(void* const* d_in, const int* in_sizes, int n_in,
                              void* d_out, int out_size)
{
    const float* fir  = (const float*)d_in[0];
    const float* sec  = (const float*)d_in[1];
    const float* gt   = (const float*)d_in[2];
    const float* diff = (const float*)d_in[3];
    float* out = (float*)d_out;

    cost_kernel <<<dim3(SB, NTILE, 2), TILE>>>(fir, sec, gt);
    match_kernel<<<NTASK, 128>>>(fir, sec, gt);
    final_kernel<<<1, 1024>>>(diff, out);
}

// round 10
// speedup vs baseline: 1.0661x; 1.0661x over previous
#include <cuda_runtime.h>
#include <math.h>
#include <limits.h>

#define S_STAGES 3
#define BATCH    32
#define NPRIOR   2000
#define LANES    4
#define DFEAT    78          // 2 + 4 + 72
#define NOFF     72
#define SB       96
#define IMG_W_F  800.0f
#define IMG_W1_F 799.0f
#define TILE     128
#define NTILE    16          // 15 full tiles + one of 80
#define PAIRB    656         // SMEM bytes per row-pair slot (624 data + 32 pad)
#define NCAND    (NTILE * 4) // 64 candidates per column
#define NMATCH   (2 * SB * LANES)   // 768
#define NTASK    (2 * SB)           // 192
#define FIXSCALE 1099511627776.0f   // 2^40

// Scratch (device globals — no allocation allowed)
// g_cls_acc is zero at load; final_kernel re-zeroes after consuming (replay-safe).
__device__ unsigned long long g_cls_acc[2 * NPRIOR];
__device__ float g_cv[NTASK * LANES * NCAND];
__device__ int   g_ci[NTASK * LANES * NCAND];
__device__ int   g_rows[NMATCH];
__device__ float g_reg [NMATCH];
__device__ float g_iou [NMATCH];
__device__ float g_corr[NMATCH];

__device__ __forceinline__ void cp_async16(unsigned s, const void* g) {
    asm volatile("cp.async.cg.shared.global [%0], [%1], 16;\n" :: "r"(s), "l"(g));
}
__device__ __forceinline__ void cp_commit() {
    asm volatile("cp.async.commit_group;\n" ::: "memory");
}
__device__ __forceinline__ void cp_wait0() {
    asm volatile("cp.async.wait_group 0;\n" ::: "memory");
}

// ---------------------------------------------------------------------------
// Kernel 1: flat 16B-chunk staged cost + candidate top-4 + fixed-point cls RED.
// Row pairs (624 B) staged flat into 656 B slots; conflict-free float2 reads.
// grid (96, NTILE, 2), 128 threads.
// ---------------------------------------------------------------------------
__global__ __launch_bounds__(TILE) void cost_kernel(
    const float* __restrict__ predA,
    const float* __restrict__ predB,
    const float* __restrict__ gt)
{
    const int sb     = blockIdx.x;
    const int tile   = blockIdx.y;
    const int branch = blockIdx.z;
    const int n0     = tile * TILE;
    const int T      = (n0 + TILE <= NPRIOR) ? TILE : (NPRIOR - n0);
    const int NP     = T >> 1;                 // row pairs (64 or 40)
    const float* __restrict__ pred = branch ? predB : predA;
    const int b = sb % BATCH;
    const char* gbase = (const char*)(pred + ((size_t)sb * NPRIOR + n0) * DFEAT);
    const size_t bs = (size_t)branch * SB + sb;

    __shared__ __align__(16) char  sh_buf[(TILE / 2) * PAIRB];  // 41984 B
    __shared__ __align__(16) float sh_gt8[39][8];   // per-dim-pair gt, lanes interleaved
    __shared__ float sh_geo[LANES][4];
    __shared__ float sh_c[LANES][TILE];

    const int tid  = threadIdx.x;
    const int warp = tid >> 5, lane = tid & 31;
    const unsigned FULL = 0xffffffffu;
    const unsigned sp = (unsigned)__cvta_generic_to_shared(sh_buf);

    // ---- stage: pair = tid>>1, 2 threads per pair, 16B chunks
    {
        const int pair = tid >> 1;
        if (pair < NP) {
            const unsigned sdst = sp + (unsigned)pair * PAIRB;
            const char*    gsrc = gbase + (size_t)pair * 624;
            #pragma unroll
            for (int c = (tid & 1); c < 39; c += 2)
                cp_async16(sdst + c * 16, gsrc + c * 16);
        }
        cp_commit();
    }

    // gt tables (overlap with async loads)
    // sh_gt8[k][2*l+comp] = gt[b,l,2k+comp]/799 for dims in [6,78), else 0
    for (int i = tid; i < 39 * 8; i += TILE) {
        int k = i >> 3, j = i & 7;
        int l = j >> 1, comp = j & 1;
        int d = 2 * k + comp;
        float v = 0.0f;
        if (d >= 6 && d < DFEAT)
            v = gt[((size_t)b * LANES + l) * DFEAT + d] * (1.0f / IMG_W1_F);
        sh_gt8[k][j] = v;
    }
    if (tid < 16)
        sh_geo[tid >> 2][tid & 3] =
            gt[((size_t)b * LANES + (tid >> 2)) * DFEAT + 2 + (tid & 3)];

    cp_wait0();
    __syncthreads();

    // ---- compute: one thread per row, float2 reads (conflict-free layout)
    if (tid < T) {
        const char* rb = sh_buf + (tid >> 1) * PAIRB + (tid & 1) * 312;
        float2 q0 = *(const float2*)(rb);        // d0,d1 logits
        float2 q1 = *(const float2*)(rb + 8);    // d2,d3
        float2 q2 = *(const float2*)(rb + 16);   // d4,d5

        float cg[LANES], o[LANES];
        #pragma unroll
        for (int l = 0; l < LANES; l++) {
            cg[l] = fabsf(q1.x - sh_geo[l][0]) + fabsf(q1.y - sh_geo[l][1])
                  + fabsf(q2.x - sh_geo[l][2]) + fabsf(q2.y - sh_geo[l][3]);
            o[l] = 0.0f;
        }
        #pragma unroll
        for (int k = 3; k < 39; k++) {           // dims 6..77
            float2 pv = *(const float2*)(rb + k * 8);
            float4 ga = *(const float4*)&sh_gt8[k][0];   // lanes 0,1
            float4 gb = *(const float4*)&sh_gt8[k][4];   // lanes 2,3
            o[0] += fabsf(pv.x - ga.x) + fabsf(pv.y - ga.y);
            o[1] += fabsf(pv.x - ga.z) + fabsf(pv.y - ga.w);
            o[2] += fabsf(pv.x - gb.x) + fabsf(pv.y - gb.y);
            o[3] += fabsf(pv.x - gb.z) + fabsf(pv.y - gb.w);
        }

        float x0 = q0.x, x1 = q0.y;
        float m  = fmaxf(x0, x1);
        float e0 = expf(x0 - m), e1 = expf(x1 - m);
        float denom = e0 + e1;
        float score = e1 / denom;
        #pragma unroll
        for (int l = 0; l < LANES; l++)
            sh_c[l][tid] = cg[l] + o[l] * (1.0f / 72.0f) - score;

        float lse = m + logf(denom);
        float om0 = 1.0f - e0 / denom;
        float cneg = -0.1f * om0 * om0 * (x0 - lse);
        atomicAdd(&g_cls_acc[branch * NPRIOR + n0 + tid],
                  (unsigned long long)(long long)__float2ll_rn(cneg * FIXSCALE));
    } else {
        #pragma unroll
        for (int l = 0; l < LANES; l++) sh_c[l][tid] = INFINITY;
    }
    __syncthreads();

    // ---- warp w: top-4 of column w within tile, first-index tie-break
    {
        const int w = warp;
        const size_t base = ((bs * LANES + w) * NTILE + tile) * 4;
        #pragma unroll
        for (int pass = 0; pass < 4; pass++) {
            float v = INFINITY; int li = INT_MAX;
            #pragma unroll
            for (int j0 = 0; j0 < TILE; j0 += 32) {
                int j = j0 + lane;
                float cc = sh_c[w][j];
                if (cc < v || (cc == v && j < li)) { v = cc; li = j; }
            }
            #pragma unroll
            for (int off = 16; off; off >>= 1) {
                float v2 = __shfl_xor_sync(FULL, v, off);
                int   i2 = __shfl_xor_sync(FULL, li, off);
                if (v2 < v || (v2 == v && i2 < li)) { v = v2; li = i2; }
            }
            if (lane == 0) {
                g_cv[base + pass] = v;
                g_ci[base + pass] = n0 + li;
                sh_c[w][li] = INFINITY;
            }
            __syncwarp(FULL);
        }
    }
}

// ---------------------------------------------------------------------------
// Kernel 2: per-task greedy merge + reg/iou/corr. grid 192, 128 threads.
// ---------------------------------------------------------------------------
__global__ __launch_bounds__(128) void match_kernel(
    const float* __restrict__ predA,
    const float* __restrict__ predB,
    const float* __restrict__ gt)
{
    const int task   = blockIdx.x;             // 0..191
    const int branch = task / SB;
    const int sb     = task % SB;
    const int b      = sb % BATCH;

    __shared__ int rows_sh[LANES];

    const int tid  = threadIdx.x;
    const int warp = tid >> 5, lane = tid & 31;
    const unsigned FULL = 0xffffffffu;

    if (warp == 0) {
        const size_t base = (size_t)task * LANES * NCAND;
        float cv[LANES][2]; int ci[LANES][2];
        #pragma unroll
        for (int col = 0; col < LANES; col++) {
            cv[col][0] = g_cv[base + col * NCAND + lane];
            cv[col][1] = g_cv[base + col * NCAND + 32 + lane];
            ci[col][0] = g_ci[base + col * NCAND + lane];
            ci[col][1] = g_ci[base + col * NCAND + 32 + lane];
        }
        int u0 = -1, u1 = -1, u2 = -1;
        #pragma unroll
        for (int col = 0; col < LANES; col++) {
            float v = INFINITY; int li = INT_MAX;
            #pragma unroll
            for (int k = 0; k < 2; k++) {
                int   i2 = ci[col][k];
                float v2 = cv[col][k];
                bool excl = (i2 == u0) | (i2 == u1) | (i2 == u2);
                if (!excl && (v2 < v || (v2 == v && i2 < li))) { v = v2; li = i2; }
            }
            #pragma unroll
            for (int off = 16; off; off >>= 1) {
                float v2 = __shfl_xor_sync(FULL, v, off);
                int   i2 = __shfl_xor_sync(FULL, li, off);
                if (v2 < v || (v2 == v && i2 < li)) { v = v2; li = i2; }
            }
            if (lane == 0) { rows_sh[col] = li; g_rows[task * LANES + col] = li; }
            if (col == 0) u0 = li; else if (col == 1) u1 = li; else if (col == 2) u2 = li;
        }
    }
    __syncthreads();

    {
        const int l = warp;
        const int r = rows_sh[l];
        const int mm = task * LANES + l;
        const float* p  = (branch ? predB : predA)
                          + ((size_t)sb * NPRIOR + r) * DFEAT;
        const float* tg = gt + ((size_t)b * LANES + l) * DFEAT;

        float ovrS = 0.0f, uniS = 0.0f;
        #pragma unroll
        for (int kb = 0; kb < 3; kb++) {
            int k = kb * 32 + lane;
            if (k < NOFF) {
                float rp = p[6 + k] * IMG_W1_F;
                float rt = tg[6 + k];
                bool invalid = (rt < 0.0f) || (rt >= IMG_W_F);
                float mn = fminf(rp, rt), mx = fmaxf(rp, rt);
                if (!invalid) {
                    ovrS += (mn - mx + 30.0f);
                    uniS += (mx - mn + 30.0f);
                }
            }
        }
        #pragma unroll
        for (int off = 16; off; off >>= 1) {
            ovrS += __shfl_xor_sync(FULL, ovrS, off);
            uniS += __shfl_xor_sync(FULL, uniS, off);
        }
        if (lane == 0) {
            float iou = ovrS / (uniS + 1e-9f);
            g_iou[mm] = (1.0f - iou) * 0.25f;
            const float sc[4] = {71.0f, IMG_W1_F, 180.0f, 71.0f};
            float ssum = 0.0f;
            #pragma unroll
            for (int j = 0; j < 4; j++) {
                float d  = (p[2 + j] - tg[2 + j]) * sc[j];
                float ad = fabsf(d);
                ssum += (ad < 1.0f) ? 0.5f * d * d : ad - 0.5f;
            }
            g_reg[mm] = ssum * 0.0625f;   // mean over 4, /L

            float x0 = p[0], x1 = p[1];
            float m2  = fmaxf(x0, x1);
            float e0 = expf(x0 - m2), e1 = expf(x1 - m2);
            float denom = e0 + e1;
            float lse = m2 + logf(denom);
            float om0 = 1.0f - e0 / denom, om1 = 1.0f - e1 / denom;
            float cneg = -0.1f * om0 * om0 * (x0 - lse);
            float cpos = -0.9f * om1 * om1 * (x1 - lse);
            g_corr[mm] = (cpos - cneg) * (2.0f / 96.0f);
        }
    }
}

// ---------------------------------------------------------------------------
// Kernel 3: inst build + corrections + dual-rank radix median + weighted sum.
// Single block, 1024 threads.
// ---------------------------------------------------------------------------
__global__ __launch_bounds__(1024) void final_kernel(
    const float* __restrict__ diff,
    float* __restrict__ out)
{
    __shared__ float instA[NPRIOR];
    __shared__ float instB[NPRIOR];
    __shared__ unsigned ukey[NPRIOR];
    __shared__ int   hist[2][256];
    __shared__ float red[1024];
    __shared__ int   s_bin[2], s_k[2];

    const int tid = threadIdx.x;
    const int warp = tid >> 5, lane = tid & 31;
    const unsigned FULL = 0xffffffffu;

    const float CLS_K = (float)(2.0 / 96.0 / 1099511627776.0);
    for (int n = tid; n < NPRIOR; n += 1024) {
        long long a0 = (long long)g_cls_acc[n];
        long long b0 = (long long)g_cls_acc[NPRIOR + n];
        instA[n] = (float)a0 * CLS_K;
        instB[n] = (float)b0 * CLS_K;
        g_cls_acc[n] = 0ull;
        g_cls_acc[NPRIOR + n] = 0ull;
    }
    __syncthreads();

    if (tid < NMATCH) {
        const int branch = tid / (SB * LANES);
        const int r = g_rows[tid];
        atomicAdd(branch == 0 ? &instA[r] : &instB[r], g_corr[tid]);
    }
    if (tid >= 1016) {
        const int t = tid - 1016;
        const int branch = t >> 2, l = t & 3;
        float rs = 0.0f, is = 0.0f;
        #pragma unroll 8
        for (int i = 0; i < SB; i++) {
            rs += g_reg[(branch * SB + i) * LANES + l];
            is += g_iou[(branch * SB + i) * LANES + l];
        }
        float add = rs * (0.5f / 96.0f) + is * (2.0f / 96.0f);
        int r = g_rows[(branch * SB + (SB - 1)) * LANES + l];
        atomicAdd(branch == 0 ? &instA[r] : &instB[r], add);
    }
    __syncthreads();

    for (int n = tid; n < NPRIOR; n += 1024) {
        float f = instA[n] - instB[n];
        unsigned x = __float_as_uint(f);
        ukey[n] = (x & 0x80000000u) ? ~x : (x | 0x80000000u);
    }
    __syncthreads();

    unsigned prefix[2] = {0u, 0u};
    unsigned mask = 0u;
    int kk[2] = {999, 1000};
    for (int shift = 24; shift >= 0; shift -= 8) {
        if (tid < 512) hist[tid >> 8][tid & 255] = 0;
        __syncthreads();
        for (int n = tid; n < NPRIOR; n += 1024) {
            unsigned u = ukey[n];
            unsigned bin = (u >> shift) & 255u;
            unsigned hi = u & mask;
            if (hi == prefix[0]) atomicAdd(&hist[0][bin], 1);
            if (hi == prefix[1]) atomicAdd(&hist[1][bin], 1);
        }
        __syncthreads();
        if (tid < 64) {
            const int trk = warp;
            int kt = kk[trk];
            int cnt[8]; int local = 0;
            #pragma unroll
            for (int k2 = 0; k2 < 8; k2++) { cnt[k2] = hist[trk][lane * 8 + k2]; local += cnt[k2]; }
            int pre = local;
            #pragma unroll
            for (int off = 1; off < 32; off <<= 1) {
                int t2 = __shfl_up_sync(FULL, pre, off);
                if (lane >= off) pre += t2;
            }
            int run = pre - local;
            int foundk = -1, myrun = 0;
            #pragma unroll
            for (int k2 = 0; k2 < 8; k2++) {
                if (foundk < 0 && kt >= run && kt < run + cnt[k2]) { foundk = k2; myrun = run; }
                run += cnt[k2];
            }
            unsigned bm = __ballot_sync(FULL, foundk >= 0);
            int src = __ffs(bm) - 1;
            if (lane == src) { s_bin[trk] = lane * 8 + foundk; s_k[trk] = kt - myrun; }
        }
        __syncthreads();
        prefix[0] |= ((unsigned)s_bin[0]) << shift;
        prefix[1] |= ((unsigned)s_bin[1]) << shift;
        mask |= 0xFFu << shift;
        kk[0] = s_k[0]; kk[1] = s_k[1];
        __syncthreads();
    }
    float m0 = (prefix[0] & 0x80000000u) ? __uint_as_float(prefix[0] ^ 0x80000000u)
                                         : __uint_as_float(~prefix[0]);
    float m1 = (prefix[1] & 0x80000000u) ? __uint_as_float(prefix[1] ^ 0x80000000u)
                                         : __uint_as_float(~prefix[1]);
    float delta = 0.5f * (m0 + m1);

    float acc = 0.0f;
    for (int n = tid; n < NPRIOR; n += 1024) {
        float dm = (diff[n] + diff[NPRIOR + n] + diff[2 * NPRIOR + n]) * (1.0f / 3.0f);
        acc += (1.0f - dm) * (instA[n] - 0.5f * delta)
             + dm          * (instB[n] + 0.5f * delta);
    }
    red[tid] = acc;
    __syncthreads();
    for (int off = 512; off; off >>= 1) {
        if (tid < off) red[tid] += red[tid + off];
        __syncthreads();
    }
    if (tid == 0) out[0] = red[0];
}

// ---------------------------------------------------------------------------
extern "C" void kernel_launch(void* const* d_in, const int* in_sizes, int n_in,
                              void* d_out, int out_size)
{
    const float* fir  = (const float*)d_in[0];
    const float* sec  = (const float*)d_in[1];
    const float* gt   = (const float*)d_in[2];
    const float* diff = (const float*)d_in[3];
    float* out = (float*)d_out;

    cost_kernel <<<dim3(SB, NTILE, 2), TILE>>>(fir, sec, gt);
    match_kernel<<<NTASK, 128>>>(fir, sec, gt);
    final_kernel<<<1, 1024>>>(diff, out);
}

// round 11
// speedup vs baseline: 1.1102x; 1.0413x over previous
#include <cuda_runtime.h>
#include <math.h>
#include <limits.h>

#define S_STAGES 3
#define BATCH    32
#define NPRIOR   2000
#define LANES    4
#define DFEAT    78          // 2 + 4 + 72
#define NOFF     72
#define SB       96
#define IMG_W_F  800.0f
#define IMG_W1_F 799.0f
#define TILE     128
#define NTILE    16          // 15 full tiles + one of 80
#define PAIRB    656         // SMEM bytes per row-pair slot (624 data + 32 pad)
#define NCAND    (NTILE * 4) // 64 candidates per column
#define NMATCH   (2 * SB * LANES)   // 768
#define NTASK    (2 * SB)           // 192
#define FIXSCALE 1099511627776.0f   // 2^40

// Scratch (device globals — no allocation allowed)
// g_cls_acc is zero at load; final_kernel re-zeroes after consuming (replay-safe).
__device__ unsigned long long g_cls_acc[2 * NPRIOR];
__device__ float g_cv[NTASK * LANES * NCAND];
__device__ int   g_ci[NTASK * LANES * NCAND];
__device__ int   g_rows[NMATCH];
__device__ float g_reg [NMATCH];
__device__ float g_iou [NMATCH];
__device__ float g_corr[NMATCH];

__device__ __forceinline__ void cp_async16(unsigned s, const void* g) {
    asm volatile("cp.async.cg.shared.global [%0], [%1], 16;\n" :: "r"(s), "l"(g));
}
__device__ __forceinline__ void cp_commit() {
    asm volatile("cp.async.commit_group;\n" ::: "memory");
}
__device__ __forceinline__ void cp_wait0() {
    asm volatile("cp.async.wait_group 0;\n" ::: "memory");
}

// ---------------------------------------------------------------------------
// Kernel 1: 256 threads, 2 threads per row (split k-loop), pair-staged SMEM.
// grid (96, NTILE, 2).
// ---------------------------------------------------------------------------
__global__ __launch_bounds__(256) void cost_kernel(
    const float* __restrict__ predA,
    const float* __restrict__ predB,
    const float* __restrict__ gt)
{
    const int sb     = blockIdx.x;
    const int tile   = blockIdx.y;
    const int branch = blockIdx.z;
    const int n0     = tile * TILE;
    const int T      = (n0 + TILE <= NPRIOR) ? TILE : (NPRIOR - n0);
    const int NP     = T >> 1;                 // row pairs (64 or 40)
    const float* __restrict__ pred = branch ? predB : predA;
    const int b = sb % BATCH;
    const char* gbase = (const char*)(pred + ((size_t)sb * NPRIOR + n0) * DFEAT);
    const size_t bs = (size_t)branch * SB + sb;

    __shared__ __align__(16) char  sh_buf[(TILE / 2) * PAIRB];  // 41984 B
    __shared__ __align__(16) float sh_gt8[39][8];   // per-dim-pair gt, lanes interleaved
    __shared__ float sh_geo[LANES][4];
    __shared__ float sh_c[LANES][TILE];
    __shared__ float sh_o2[LANES][TILE];            // half-1 partial sums

    const int tid  = threadIdx.x;
    const int warp = tid >> 5, lane = tid & 31;
    const unsigned FULL = 0xffffffffu;
    const unsigned sp = (unsigned)__cvta_generic_to_shared(sh_buf);

    // ---- stage: 4 threads per pair, 16B chunks
    {
        const int pair = tid >> 2;
        if (pair < NP) {
            const unsigned sdst = sp + (unsigned)pair * PAIRB;
            const char*    gsrc = gbase + (size_t)pair * 624;
            #pragma unroll
            for (int c = (tid & 3); c < 39; c += 4)
                cp_async16(sdst + c * 16, gsrc + c * 16);
        }
        cp_commit();
    }

    // gt tables (overlap with async loads)
    for (int i = tid; i < 39 * 8; i += 256) {
        int k = i >> 3, j = i & 7;
        int l = j >> 1, comp = j & 1;
        int d = 2 * k + comp;
        float v = 0.0f;
        if (d >= 6 && d < DFEAT)
            v = gt[((size_t)b * LANES + l) * DFEAT + d] * (1.0f / IMG_W1_F);
        sh_gt8[k][j] = v;
    }
    if (tid < 16)
        sh_geo[tid >> 2][tid & 3] =
            gt[((size_t)b * LANES + (tid >> 2)) * DFEAT + 2 + (tid & 3)];

    cp_wait0();
    __syncthreads();

    // ---- compute: 2 threads per row. half0: geo + k=3..20 + logits;
    //               half1: k=21..38 -> sh_o2. Both halves run concurrently.
    const int row  = tid & 127;
    const int half = tid >> 7;
    const char* rb = sh_buf + (row >> 1) * PAIRB + (row & 1) * 312;

    float cg[LANES], o[LANES];
    float x0 = 0.0f, x1 = 0.0f;
    if (row < T) {
        if (half == 1) {
            float o2[LANES] = {0.0f, 0.0f, 0.0f, 0.0f};
            #pragma unroll
            for (int k = 21; k < 39; k++) {
                float2 pv = *(const float2*)(rb + k * 8);
                float4 ga = *(const float4*)&sh_gt8[k][0];
                float4 gb = *(const float4*)&sh_gt8[k][4];
                o2[0] += fabsf(pv.x - ga.x) + fabsf(pv.y - ga.y);
                o2[1] += fabsf(pv.x - ga.z) + fabsf(pv.y - ga.w);
                o2[2] += fabsf(pv.x - gb.x) + fabsf(pv.y - gb.y);
                o2[3] += fabsf(pv.x - gb.z) + fabsf(pv.y - gb.w);
            }
            #pragma unroll
            for (int l = 0; l < LANES; l++) sh_o2[l][row] = o2[l];
        } else {
            float2 q0 = *(const float2*)(rb);        // d0,d1 logits
            float2 q1 = *(const float2*)(rb + 8);    // d2,d3
            float2 q2 = *(const float2*)(rb + 16);   // d4,d5
            x0 = q0.x; x1 = q0.y;
            #pragma unroll
            for (int l = 0; l < LANES; l++) {
                cg[l] = fabsf(q1.x - sh_geo[l][0]) + fabsf(q1.y - sh_geo[l][1])
                      + fabsf(q2.x - sh_geo[l][2]) + fabsf(q2.y - sh_geo[l][3]);
                o[l] = 0.0f;
            }
            #pragma unroll
            for (int k = 3; k < 21; k++) {
                float2 pv = *(const float2*)(rb + k * 8);
                float4 ga = *(const float4*)&sh_gt8[k][0];
                float4 gb = *(const float4*)&sh_gt8[k][4];
                o[0] += fabsf(pv.x - ga.x) + fabsf(pv.y - ga.y);
                o[1] += fabsf(pv.x - ga.z) + fabsf(pv.y - ga.w);
                o[2] += fabsf(pv.x - gb.x) + fabsf(pv.y - gb.y);
                o[3] += fabsf(pv.x - gb.z) + fabsf(pv.y - gb.w);
            }
        }
    }
    __syncthreads();

    if (half == 0) {
        if (row < T) {
            float m  = fmaxf(x0, x1);
            float e0 = expf(x0 - m), e1 = expf(x1 - m);
            float denom = e0 + e1;
            float score = e1 / denom;
            #pragma unroll
            for (int l = 0; l < LANES; l++)
                sh_c[l][row] = cg[l] + (o[l] + sh_o2[l][row]) * (1.0f / 72.0f) - score;

            float lse = m + logf(denom);
            float om0 = 1.0f - e0 / denom;
            float cneg = -0.1f * om0 * om0 * (x0 - lse);
            atomicAdd(&g_cls_acc[branch * NPRIOR + n0 + row],
                      (unsigned long long)(long long)__float2ll_rn(cneg * FIXSCALE));
        } else {
            #pragma unroll
            for (int l = 0; l < LANES; l++) sh_c[l][row] = INFINITY;
        }
    }
    __syncthreads();

    // ---- warps 0..3: top-4 of column w within tile, first-index tie-break
    if (warp < LANES) {
        const int w = warp;
        const size_t base = ((bs * LANES + w) * NTILE + tile) * 4;
        #pragma unroll
        for (int pass = 0; pass < 4; pass++) {
            float v = INFINITY; int li = INT_MAX;
            #pragma unroll
            for (int j0 = 0; j0 < TILE; j0 += 32) {
                int j = j0 + lane;
                float cc = sh_c[w][j];
                if (cc < v || (cc == v && j < li)) { v = cc; li = j; }
            }
            #pragma unroll
            for (int off = 16; off; off >>= 1) {
                float v2 = __shfl_xor_sync(FULL, v, off);
                int   i2 = __shfl_xor_sync(FULL, li, off);
                if (v2 < v || (v2 == v && i2 < li)) { v = v2; li = i2; }
            }
            if (lane == 0) {
                g_cv[base + pass] = v;
                g_ci[base + pass] = n0 + li;
                sh_c[w][li] = INFINITY;
            }
            __syncwarp(FULL);
        }
    }
}

// ---------------------------------------------------------------------------
// Kernel 2: per-task greedy merge + reg/iou/corr. grid 192, 128 threads.
// ---------------------------------------------------------------------------
__global__ __launch_bounds__(128) void match_kernel(
    const float* __restrict__ predA,
    const float* __restrict__ predB,
    const float* __restrict__ gt)
{
    const int task   = blockIdx.x;             // 0..191
    const int branch = task / SB;
    const int sb     = task % SB;
    const int b      = sb % BATCH;

    __shared__ int rows_sh[LANES];

    const int tid  = threadIdx.x;
    const int warp = tid >> 5, lane = tid & 31;
    const unsigned FULL = 0xffffffffu;

    if (warp == 0) {
        const size_t base = (size_t)task * LANES * NCAND;
        float cv[LANES][2]; int ci[LANES][2];
        #pragma unroll
        for (int col = 0; col < LANES; col++) {
            cv[col][0] = g_cv[base + col * NCAND + lane];
            cv[col][1] = g_cv[base + col * NCAND + 32 + lane];
            ci[col][0] = g_ci[base + col * NCAND + lane];
            ci[col][1] = g_ci[base + col * NCAND + 32 + lane];
        }
        int u0 = -1, u1 = -1, u2 = -1;
        #pragma unroll
        for (int col = 0; col < LANES; col++) {
            float v = INFINITY; int li = INT_MAX;
            #pragma unroll
            for (int k = 0; k < 2; k++) {
                int   i2 = ci[col][k];
                float v2 = cv[col][k];
                bool excl = (i2 == u0) | (i2 == u1) | (i2 == u2);
                if (!excl && (v2 < v || (v2 == v && i2 < li))) { v = v2; li = i2; }
            }
            #pragma unroll
            for (int off = 16; off; off >>= 1) {
                float v2 = __shfl_xor_sync(FULL, v, off);
                int   i2 = __shfl_xor_sync(FULL, li, off);
                if (v2 < v || (v2 == v && i2 < li)) { v = v2; li = i2; }
            }
            if (lane == 0) { rows_sh[col] = li; g_rows[task * LANES + col] = li; }
            if (col == 0) u0 = li; else if (col == 1) u1 = li; else if (col == 2) u2 = li;
        }
    }
    __syncthreads();

    {
        const int l = warp;
        const int r = rows_sh[l];
        const int mm = task * LANES + l;
        const float* p  = (branch ? predB : predA)
                          + ((size_t)sb * NPRIOR + r) * DFEAT;
        const float* tg = gt + ((size_t)b * LANES + l) * DFEAT;

        float ovrS = 0.0f, uniS = 0.0f;
        #pragma unroll
        for (int kb = 0; kb < 3; kb++) {
            int k = kb * 32 + lane;
            if (k < NOFF) {
                float rp = p[6 + k] * IMG_W1_F;
                float rt = tg[6 + k];
                bool invalid = (rt < 0.0f) || (rt >= IMG_W_F);
                float mn = fminf(rp, rt), mx = fmaxf(rp, rt);
                if (!invalid) {
                    ovrS += (mn - mx + 30.0f);
                    uniS += (mx - mn + 30.0f);
                }
            }
        }
        #pragma unroll
        for (int off = 16; off; off >>= 1) {
            ovrS += __shfl_xor_sync(FULL, ovrS, off);
            uniS += __shfl_xor_sync(FULL, uniS, off);
        }
        if (lane == 0) {
            float iou = ovrS / (uniS + 1e-9f);
            g_iou[mm] = (1.0f - iou) * 0.25f;
            const float sc[4] = {71.0f, IMG_W1_F, 180.0f, 71.0f};
            float ssum = 0.0f;
            #pragma unroll
            for (int j = 0; j < 4; j++) {
                float d  = (p[2 + j] - tg[2 + j]) * sc[j];
                float ad = fabsf(d);
                ssum += (ad < 1.0f) ? 0.5f * d * d : ad - 0.5f;
            }
            g_reg[mm] = ssum * 0.0625f;   // mean over 4, /L

            float x0 = p[0], x1 = p[1];
            float m2  = fmaxf(x0, x1);
            float e0 = expf(x0 - m2), e1 = expf(x1 - m2);
            float denom = e0 + e1;
            float lse = m2 + logf(denom);
            float om0 = 1.0f - e0 / denom, om1 = 1.0f - e1 / denom;
            float cneg = -0.1f * om0 * om0 * (x0 - lse);
            float cpos = -0.9f * om1 * om1 * (x1 - lse);
            g_corr[mm] = (cpos - cneg) * (2.0f / 96.0f);
        }
    }
}

// ---------------------------------------------------------------------------
// Kernel 3: inst build + corrections + dual-rank radix median + weighted sum.
// Single block, 1024 threads.
// ---------------------------------------------------------------------------
__global__ __launch_bounds__(1024) void final_kernel(
    const float* __restrict__ diff,
    float* __restrict__ out)
{
    __shared__ float instA[NPRIOR];
    __shared__ float instB[NPRIOR];
    __shared__ unsigned ukey[NPRIOR];
    __shared__ int   hist[2][256];
    __shared__ float red[1024];
    __shared__ int   s_bin[2], s_k[2];

    const int tid = threadIdx.x;
    const int warp = tid >> 5, lane = tid & 31;
    const unsigned FULL = 0xffffffffu;

    const float CLS_K = (float)(2.0 / 96.0 / 1099511627776.0);
    for (int n = tid; n < NPRIOR; n += 1024) {
        long long a0 = (long long)g_cls_acc[n];
        long long b0 = (long long)g_cls_acc[NPRIOR + n];
        instA[n] = (float)a0 * CLS_K;
        instB[n] = (float)b0 * CLS_K;
        g_cls_acc[n] = 0ull;
        g_cls_acc[NPRIOR + n] = 0ull;
    }
    __syncthreads();

    if (tid < NMATCH) {
        const int branch = tid / (SB * LANES);
        const int r = g_rows[tid];
        atomicAdd(branch == 0 ? &instA[r] : &instB[r], g_corr[tid]);
    }
    if (tid >= 1016) {
        const int t = tid - 1016;
        const int branch = t >> 2, l = t & 3;
        float rs = 0.0f, is = 0.0f;
        #pragma unroll 8
        for (int i = 0; i < SB; i++) {
            rs += g_reg[(branch * SB + i) * LANES + l];
            is += g_iou[(branch * SB + i) * LANES + l];
        }
        float add = rs * (0.5f / 96.0f) + is * (2.0f / 96.0f);
        int r = g_rows[(branch * SB + (SB - 1)) * LANES + l];
        atomicAdd(branch == 0 ? &instA[r] : &instB[r], add);
    }
    __syncthreads();

    for (int n = tid; n < NPRIOR; n += 1024) {
        float f = instA[n] - instB[n];
        unsigned x = __float_as_uint(f);
        ukey[n] = (x & 0x80000000u) ? ~x : (x | 0x80000000u);
    }
    __syncthreads();

    unsigned prefix[2] = {0u, 0u};
    unsigned mask = 0u;
    int kk[2] = {999, 1000};
    for (int shift = 24; shift >= 0; shift -= 8) {
        if (tid < 512) hist[tid >> 8][tid & 255] = 0;
        __syncthreads();
        for (int n = tid; n < NPRIOR; n += 1024) {
            unsigned u = ukey[n];
            unsigned bin = (u >> shift) & 255u;
            unsigned hi = u & mask;
            if (hi == prefix[0]) atomicAdd(&hist[0][bin], 1);
            if (hi == prefix[1]) atomicAdd(&hist[1][bin], 1);
        }
        __syncthreads();
        if (tid < 64) {
            const int trk = warp;
            int kt = kk[trk];
            int cnt[8]; int local = 0;
            #pragma unroll
            for (int k2 = 0; k2 < 8; k2++) { cnt[k2] = hist[trk][lane * 8 + k2]; local += cnt[k2]; }
            int pre = local;
            #pragma unroll
            for (int off = 1; off < 32; off <<= 1) {
                int t2 = __shfl_up_sync(FULL, pre, off);
                if (lane >= off) pre += t2;
            }
            int run = pre - local;
            int foundk = -1, myrun = 0;
            #pragma unroll
            for (int k2 = 0; k2 < 8; k2++) {
                if (foundk < 0 && kt >= run && kt < run + cnt[k2]) { foundk = k2; myrun = run; }
                run += cnt[k2];
            }
            unsigned bm = __ballot_sync(FULL, foundk >= 0);
            int src = __ffs(bm) - 1;
            if (lane == src) { s_bin[trk] = lane * 8 + foundk; s_k[trk] = kt - myrun; }
        }
        __syncthreads();
        prefix[0] |= ((unsigned)s_bin[0]) << shift;
        prefix[1] |= ((unsigned)s_bin[1]) << shift;
        mask |= 0xFFu << shift;
        kk[0] = s_k[0]; kk[1] = s_k[1];
        __syncthreads();
    }
    float m0 = (prefix[0] & 0x80000000u) ? __uint_as_float(prefix[0] ^ 0x80000000u)
                                         : __uint_as_float(~prefix[0]);
    float m1 = (prefix[1] & 0x80000000u) ? __uint_as_float(prefix[1] ^ 0x80000000u)
                                         : __uint_as_float(~prefix[1]);
    float delta = 0.5f * (m0 + m1);

    float acc = 0.0f;
    for (int n = tid; n < NPRIOR; n += 1024) {
        float dm = (diff[n] + diff[NPRIOR + n] + diff[2 * NPRIOR + n]) * (1.0f / 3.0f);
        acc += (1.0f - dm) * (instA[n] - 0.5f * delta)
             + dm          * (instB[n] + 0.5f * delta);
    }
    red[tid] = acc;
    __syncthreads();
    for (int off = 512; off; off >>= 1) {
        if (tid < off) red[tid] += red[tid + off];
        __syncthreads();
    }
    if (tid == 0) out[0] = red[0];
}

// ---------------------------------------------------------------------------
extern "C" void kernel_launch(void* const* d_in, const int* in_sizes, int n_in,
                              void* d_out, int out_size)
{
    const float* fir  = (const float*)d_in[0];
    const float* sec  = (const float*)d_in[1];
    const float* gt   = (const float*)d_in[2];
    const float* diff = (const float*)d_in[3];
    float* out = (float*)d_out;

    cost_kernel <<<dim3(SB, NTILE, 2), 256>>>(fir, sec, gt);
    match_kernel<<<NTASK, 128>>>(fir, sec, gt);
    final_kernel<<<1, 1024>>>(diff, out);
}

// round 12
// speedup vs baseline: 1.1587x; 1.0437x over previous
#include <cuda_runtime.h>
#include <math.h>
#include <limits.h>

#define S_STAGES 3
#define BATCH    32
#define NPRIOR   2000
#define LANES    4
#define DFEAT    78          // 2 + 4 + 72
#define NOFF     72
#define SB       96
#define IMG_W_F  800.0f
#define IMG_W1_F 799.0f
#define TILE     128
#define NTILE    16          // 15 full tiles + one of 80
#define PAIRB    656         // SMEM bytes per row-pair slot (624 data + 32 pad)
#define NCAND    (NTILE * 4) // 64 candidates per column
#define NMATCH   (2 * SB * LANES)   // 768
#define NTASK    (2 * SB)           // 192
#define FIXSCALE 1099511627776.0f   // 2^40

// Scratch (device globals — no allocation allowed)
// g_cls_acc is zero at load; final_kernel re-zeroes after consuming (replay-safe).
__device__ unsigned long long g_cls_acc[2 * NPRIOR];
__device__ float g_cv[NTASK * LANES * NCAND];
__device__ int   g_ci[NTASK * LANES * NCAND];
__device__ int   g_rows[NMATCH];
__device__ float g_reg [NMATCH];
__device__ float g_iou [NMATCH];
__device__ float g_corr[NMATCH];

__device__ __forceinline__ void cp_async16(unsigned s, const void* g) {
    asm volatile("cp.async.cg.shared.global [%0], [%1], 16;\n" :: "r"(s), "l"(g));
}
__device__ __forceinline__ void cp_commit() {
    asm volatile("cp.async.commit_group;\n" ::: "memory");
}
__device__ __forceinline__ void cp_wait0() {
    asm volatile("cp.async.wait_group 0;\n" ::: "memory");
}

// ---------------------------------------------------------------------------
// Kernel 1: 256 threads, 2 threads per row (split k-loop), pair-staged SMEM.
// __launch_bounds__(256,5): cap regs at 51 so 5 blocks/SM fit the RF.
// sh_acc doubles as half-1 partial buffer AND final cost buffer (union).
// grid (96, NTILE, 2).
// ---------------------------------------------------------------------------
__global__ __launch_bounds__(256, 5) void cost_kernel(
    const float* __restrict__ predA,
    const float* __restrict__ predB,
    const float* __restrict__ gt)
{
    const int sb     = blockIdx.x;
    const int tile   = blockIdx.y;
    const int branch = blockIdx.z;
    const int n0     = tile * TILE;
    const int T      = (n0 + TILE <= NPRIOR) ? TILE : (NPRIOR - n0);
    const int NP     = T >> 1;                 // row pairs (64 or 40)
    const float* __restrict__ pred = branch ? predB : predA;
    const int b = sb % BATCH;
    const char* gbase = (const char*)(pred + ((size_t)sb * NPRIOR + n0) * DFEAT);
    const size_t bs = (size_t)branch * SB + sb;

    __shared__ __align__(16) char  sh_buf[(TILE / 2) * PAIRB];  // 41984 B
    __shared__ __align__(16) float sh_gt8[39][8];   // per-dim-pair gt, lanes interleaved
    __shared__ float sh_geo[LANES][4];
    __shared__ float sh_acc[LANES][TILE];           // half-1 partials, then final costs

    const int tid  = threadIdx.x;
    const int warp = tid >> 5, lane = tid & 31;
    const unsigned FULL = 0xffffffffu;
    const unsigned sp = (unsigned)__cvta_generic_to_shared(sh_buf);

    // ---- stage: 4 threads per pair, 16B chunks
    {
        const int pair = tid >> 2;
        if (pair < NP) {
            const unsigned sdst = sp + (unsigned)pair * PAIRB;
            const char*    gsrc = gbase + (size_t)pair * 624;
            #pragma unroll
            for (int c = (tid & 3); c < 39; c += 4)
                cp_async16(sdst + c * 16, gsrc + c * 16);
        }
        cp_commit();
    }

    // gt tables (overlap with async loads)
    for (int i = tid; i < 39 * 8; i += 256) {
        int k = i >> 3, j = i & 7;
        int l = j >> 1, comp = j & 1;
        int d = 2 * k + comp;
        float v = 0.0f;
        if (d >= 6 && d < DFEAT)
            v = gt[((size_t)b * LANES + l) * DFEAT + d] * (1.0f / IMG_W1_F);
        sh_gt8[k][j] = v;
    }
    if (tid < 16)
        sh_geo[tid >> 2][tid & 3] =
            gt[((size_t)b * LANES + (tid >> 2)) * DFEAT + 2 + (tid & 3)];

    cp_wait0();
    __syncthreads();

    // ---- compute: 2 threads per row (warps 0-3: half0, warps 4-7: half1)
    const int row  = tid & 127;
    const int half = tid >> 7;
    const char* rb = sh_buf + (row >> 1) * PAIRB + (row & 1) * 312;

    float cg[LANES], o[LANES];
    float x0 = 0.0f, x1 = 0.0f;
    if (row < T) {
        if (half == 1) {
            float o2[LANES] = {0.0f, 0.0f, 0.0f, 0.0f};
            #pragma unroll
            for (int k = 21; k < 39; k++) {
                float2 pv = *(const float2*)(rb + k * 8);
                float4 ga = *(const float4*)&sh_gt8[k][0];
                float4 gb = *(const float4*)&sh_gt8[k][4];
                o2[0] += fabsf(pv.x - ga.x) + fabsf(pv.y - ga.y);
                o2[1] += fabsf(pv.x - ga.z) + fabsf(pv.y - ga.w);
                o2[2] += fabsf(pv.x - gb.x) + fabsf(pv.y - gb.y);
                o2[3] += fabsf(pv.x - gb.z) + fabsf(pv.y - gb.w);
            }
            #pragma unroll
            for (int l = 0; l < LANES; l++) sh_acc[l][row] = o2[l];
        } else {
            float2 q0 = *(const float2*)(rb);        // d0,d1 logits
            float2 q1 = *(const float2*)(rb + 8);    // d2,d3
            float2 q2 = *(const float2*)(rb + 16);   // d4,d5
            x0 = q0.x; x1 = q0.y;
            #pragma unroll
            for (int l = 0; l < LANES; l++) {
                cg[l] = fabsf(q1.x - sh_geo[l][0]) + fabsf(q1.y - sh_geo[l][1])
                      + fabsf(q2.x - sh_geo[l][2]) + fabsf(q2.y - sh_geo[l][3]);
                o[l] = 0.0f;
            }
            #pragma unroll
            for (int k = 3; k < 21; k++) {
                float2 pv = *(const float2*)(rb + k * 8);
                float4 ga = *(const float4*)&sh_gt8[k][0];
                float4 gb = *(const float4*)&sh_gt8[k][4];
                o[0] += fabsf(pv.x - ga.x) + fabsf(pv.y - ga.y);
                o[1] += fabsf(pv.x - ga.z) + fabsf(pv.y - ga.w);
                o[2] += fabsf(pv.x - gb.x) + fabsf(pv.y - gb.y);
                o[3] += fabsf(pv.x - gb.z) + fabsf(pv.y - gb.w);
            }
        }
    }
    __syncthreads();

    if (half == 0) {
        if (row < T) {
            float m  = fmaxf(x0, x1);
            float e0 = expf(x0 - m), e1 = expf(x1 - m);
            float denom = e0 + e1;
            float score = e1 / denom;
            // read half-1 partial, then overwrite SAME slot with final cost
            #pragma unroll
            for (int l = 0; l < LANES; l++) {
                float tot = o[l] + sh_acc[l][row];
                sh_acc[l][row] = cg[l] + tot * (1.0f / 72.0f) - score;
            }
            float lse = m + logf(denom);
            float om0 = 1.0f - e0 / denom;
            float cneg = -0.1f * om0 * om0 * (x0 - lse);
            atomicAdd(&g_cls_acc[branch * NPRIOR + n0 + row],
                      (unsigned long long)(long long)__float2ll_rn(cneg * FIXSCALE));
        } else {
            #pragma unroll
            for (int l = 0; l < LANES; l++) sh_acc[l][row] = INFINITY;
        }
    }
    __syncthreads();

    // ---- warps 0..3: top-4 of column w within tile, first-index tie-break
    if (warp < LANES) {
        const int w = warp;
        const size_t base = ((bs * LANES + w) * NTILE + tile) * 4;
        #pragma unroll
        for (int pass = 0; pass < 4; pass++) {
            float v = INFINITY; int li = INT_MAX;
            #pragma unroll
            for (int j0 = 0; j0 < TILE; j0 += 32) {
                int j = j0 + lane;
                float cc = sh_acc[w][j];
                if (cc < v || (cc == v && j < li)) { v = cc; li = j; }
            }
            #pragma unroll
            for (int off = 16; off; off >>= 1) {
                float v2 = __shfl_xor_sync(FULL, v, off);
                int   i2 = __shfl_xor_sync(FULL, li, off);
                if (v2 < v || (v2 == v && i2 < li)) { v = v2; li = i2; }
            }
            if (lane == 0) {
                g_cv[base + pass] = v;
                g_ci[base + pass] = n0 + li;
                sh_acc[w][li] = INFINITY;
            }
            __syncwarp(FULL);
        }
    }
}

// ---------------------------------------------------------------------------
// Kernel 2: per-task greedy merge + reg/iou/corr. grid 192, 128 threads.
// ---------------------------------------------------------------------------
__global__ __launch_bounds__(128) void match_kernel(
    const float* __restrict__ predA,
    const float* __restrict__ predB,
    const float* __restrict__ gt)
{
    const int task   = blockIdx.x;             // 0..191
    const int branch = task / SB;
    const int sb     = task % SB;
    const int b      = sb % BATCH;

    __shared__ int rows_sh[LANES];

    const int tid  = threadIdx.x;
    const int warp = tid >> 5, lane = tid & 31;
    const unsigned FULL = 0xffffffffu;

    if (warp == 0) {
        const size_t base = (size_t)task * LANES * NCAND;
        float cv[LANES][2]; int ci[LANES][2];
        #pragma unroll
        for (int col = 0; col < LANES; col++) {
            cv[col][0] = g_cv[base + col * NCAND + lane];
            cv[col][1] = g_cv[base + col * NCAND + 32 + lane];
            ci[col][0] = g_ci[base + col * NCAND + lane];
            ci[col][1] = g_ci[base + col * NCAND + 32 + lane];
        }
        int u0 = -1, u1 = -1, u2 = -1;
        #pragma unroll
        for (int col = 0; col < LANES; col++) {
            float v = INFINITY; int li = INT_MAX;
            #pragma unroll
            for (int k = 0; k < 2; k++) {
                int   i2 = ci[col][k];
                float v2 = cv[col][k];
                bool excl = (i2 == u0) | (i2 == u1) | (i2 == u2);
                if (!excl && (v2 < v || (v2 == v && i2 < li))) { v = v2; li = i2; }
            }
            #pragma unroll
            for (int off = 16; off; off >>= 1) {
                float v2 = __shfl_xor_sync(FULL, v, off);
                int   i2 = __shfl_xor_sync(FULL, li, off);
                if (v2 < v || (v2 == v && i2 < li)) { v = v2; li = i2; }
            }
            if (lane == 0) { rows_sh[col] = li; g_rows[task * LANES + col] = li; }
            if (col == 0) u0 = li; else if (col == 1) u1 = li; else if (col == 2) u2 = li;
        }
    }
    __syncthreads();

    {
        const int l = warp;
        const int r = rows_sh[l];
        const int mm = task * LANES + l;
        const float* p  = (branch ? predB : predA)
                          + ((size_t)sb * NPRIOR + r) * DFEAT;
        const float* tg = gt + ((size_t)b * LANES + l) * DFEAT;

        float ovrS = 0.0f, uniS = 0.0f;
        #pragma unroll
        for (int kb = 0; kb < 3; kb++) {
            int k = kb * 32 + lane;
            if (k < NOFF) {
                float rp = p[6 + k] * IMG_W1_F;
                float rt = tg[6 + k];
                bool invalid = (rt < 0.0f) || (rt >= IMG_W_F);
                float mn = fminf(rp, rt), mx = fmaxf(rp, rt);
                if (!invalid) {
                    ovrS += (mn - mx + 30.0f);
                    uniS += (mx - mn + 30.0f);
                }
            }
        }
        #pragma unroll
        for (int off = 16; off; off >>= 1) {
            ovrS += __shfl_xor_sync(FULL, ovrS, off);
            uniS += __shfl_xor_sync(FULL, uniS, off);
        }
        if (lane == 0) {
            float iou = ovrS / (uniS + 1e-9f);
            g_iou[mm] = (1.0f - iou) * 0.25f;
            const float sc[4] = {71.0f, IMG_W1_F, 180.0f, 71.0f};
            float ssum = 0.0f;
            #pragma unroll
            for (int j = 0; j < 4; j++) {
                float d  = (p[2 + j] - tg[2 + j]) * sc[j];
                float ad = fabsf(d);
                ssum += (ad < 1.0f) ? 0.5f * d * d : ad - 0.5f;
            }
            g_reg[mm] = ssum * 0.0625f;   // mean over 4, /L

            float x0 = p[0], x1 = p[1];
            float m2  = fmaxf(x0, x1);
            float e0 = expf(x0 - m2), e1 = expf(x1 - m2);
            float denom = e0 + e1;
            float lse = m2 + logf(denom);
            float om0 = 1.0f - e0 / denom, om1 = 1.0f - e1 / denom;
            float cneg = -0.1f * om0 * om0 * (x0 - lse);
            float cpos = -0.9f * om1 * om1 * (x1 - lse);
            g_corr[mm] = (cpos - cneg) * (2.0f / 96.0f);
        }
    }
}

// ---------------------------------------------------------------------------
// Kernel 3: inst build + corrections + dual-rank radix median + weighted sum.
// Single block, 1024 threads.
// ---------------------------------------------------------------------------
__global__ __launch_bounds__(1024) void final_kernel(
    const float* __restrict__ diff,
    float* __restrict__ out)
{
    __shared__ float instA[NPRIOR];
    __shared__ float instB[NPRIOR];
    __shared__ unsigned ukey[NPRIOR];
    __shared__ int   hist[2][256];
    __shared__ float red[1024];
    __shared__ int   s_bin[2], s_k[2];

    const int tid = threadIdx.x;
    const int warp = tid >> 5, lane = tid & 31;
    const unsigned FULL = 0xffffffffu;

    const float CLS_K = (float)(2.0 / 96.0 / 1099511627776.0);
    for (int n = tid; n < NPRIOR; n += 1024) {
        long long a0 = (long long)g_cls_acc[n];
        long long b0 = (long long)g_cls_acc[NPRIOR + n];
        instA[n] = (float)a0 * CLS_K;
        instB[n] = (float)b0 * CLS_K;
        g_cls_acc[n] = 0ull;
        g_cls_acc[NPRIOR + n] = 0ull;
    }
    __syncthreads();

    if (tid < NMATCH) {
        const int branch = tid / (SB * LANES);
        const int r = g_rows[tid];
        atomicAdd(branch == 0 ? &instA[r] : &instB[r], g_corr[tid]);
    }
    if (tid >= 1016) {
        const int t = tid - 1016;
        const int branch = t >> 2, l = t & 3;
        float rs = 0.0f, is = 0.0f;
        #pragma unroll 8
        for (int i = 0; i < SB; i++) {
            rs += g_reg[(branch * SB + i) * LANES + l];
            is += g_iou[(branch * SB + i) * LANES + l];
        }
        float add = rs * (0.5f / 96.0f) + is * (2.0f / 96.0f);
        int r = g_rows[(branch * SB + (SB - 1)) * LANES + l];
        atomicAdd(branch == 0 ? &instA[r] : &instB[r], add);
    }
    __syncthreads();

    for (int n = tid; n < NPRIOR; n += 1024) {
        float f = instA[n] - instB[n];
        unsigned x = __float_as_uint(f);
        ukey[n] = (x & 0x80000000u) ? ~x : (x | 0x80000000u);
    }
    __syncthreads();

    unsigned prefix[2] = {0u, 0u};
    unsigned mask = 0u;
    int kk[2] = {999, 1000};
    for (int shift = 24; shift >= 0; shift -= 8) {
        if (tid < 512) hist[tid >> 8][tid & 255] = 0;
        __syncthreads();
        for (int n = tid; n < NPRIOR; n += 1024) {
            unsigned u = ukey[n];
            unsigned bin = (u >> shift) & 255u;
            unsigned hi = u & mask;
            if (hi == prefix[0]) atomicAdd(&hist[0][bin], 1);
            if (hi == prefix[1]) atomicAdd(&hist[1][bin], 1);
        }
        __syncthreads();
        if (tid < 64) {
            const int trk = warp;
            int kt = kk[trk];
            int cnt[8]; int local = 0;
            #pragma unroll
            for (int k2 = 0; k2 < 8; k2++) { cnt[k2] = hist[trk][lane * 8 + k2]; local += cnt[k2]; }
            int pre = local;
            #pragma unroll
            for (int off = 1; off < 32; off <<= 1) {
                int t2 = __shfl_up_sync(FULL, pre, off);
                if (lane >= off) pre += t2;
            }
            int run = pre - local;
            int foundk = -1, myrun = 0;
            #pragma unroll
            for (int k2 = 0; k2 < 8; k2++) {
                if (foundk < 0 && kt >= run && kt < run + cnt[k2]) { foundk = k2; myrun = run; }
                run += cnt[k2];
            }
            unsigned bm = __ballot_sync(FULL, foundk >= 0);
            int src = __ffs(bm) - 1;
            if (lane == src) { s_bin[trk] = lane * 8 + foundk; s_k[trk] = kt - myrun; }
        }
        __syncthreads();
        prefix[0] |= ((unsigned)s_bin[0]) << shift;
        prefix[1] |= ((unsigned)s_bin[1]) << shift;
        mask |= 0xFFu << shift;
        kk[0] = s_k[0]; kk[1] = s_k[1];
        __syncthreads();
    }
    float m0 = (prefix[0] & 0x80000000u) ? __uint_as_float(prefix[0] ^ 0x80000000u)
                                         : __uint_as_float(~prefix[0]);
    float m1 = (prefix[1] & 0x80000000u) ? __uint_as_float(prefix[1] ^ 0x80000000u)
                                         : __uint_as_float(~prefix[1]);
    float delta = 0.5f * (m0 + m1);

    float acc = 0.0f;
    for (int n = tid; n < NPRIOR; n += 1024) {
        float dm = (diff[n] + diff[NPRIOR + n] + diff[2 * NPRIOR + n]) * (1.0f / 3.0f);
        acc += (1.0f - dm) * (instA[n] - 0.5f * delta)
             + dm          * (instB[n] + 0.5f * delta);
    }
    red[tid] = acc;
    __syncthreads();
    for (int off = 512; off; off >>= 1) {
        if (tid < off) red[tid] += red[tid + off];
        __syncthreads();
    }
    if (tid == 0) out[0] = red[0];
}

// ---------------------------------------------------------------------------
extern "C" void kernel_launch(void* const* d_in, const int* in_sizes, int n_in,
                              void* d_out, int out_size)
{
    const float* fir  = (const float*)d_in[0];
    const float* sec  = (const float*)d_in[1];
    const float* gt   = (const float*)d_in[2];
    const float* diff = (const float*)d_in[3];
    float* out = (float*)d_out;

    cost_kernel <<<dim3(SB, NTILE, 2), 256>>>(fir, sec, gt);
    match_kernel<<<NTASK, 128>>>(fir, sec, gt);
    final_kernel<<<1, 1024>>>(diff, out);
}

// round 13
// speedup vs baseline: 1.2943x; 1.1171x over previous
#include <cuda_runtime.h>
#include <math.h>
#include <limits.h>

#define S_STAGES 3
#define BATCH    32
#define NPRIOR   2000
#define LANES    4
#define DFEAT    78          // 2 + 4 + 72
#define NOFF     72
#define SB       96
#define IMG_W_F  800.0f
#define IMG_W1_F 799.0f
#define TILE     128
#define NTILE    16          // 15 full tiles + one of 80
#define ROWB     312         // bytes per row
#define NCAND    (NTILE * 4) // 64 candidates per column
#define NMATCH   (2 * SB * LANES)   // 768
#define NTASK    (2 * SB)           // 192
#define FIXSCALE 1099511627776.0f   // 2^40

// Scratch (device globals — no allocation allowed)
// g_cls_acc is zero at load; final_kernel re-zeroes after consuming (replay-safe).
__device__ unsigned long long g_cls_acc[2 * NPRIOR];
__device__ float g_cv[NTASK * LANES * NCAND];
__device__ int   g_ci[NTASK * LANES * NCAND];
__device__ int   g_rows[NMATCH];
__device__ float g_reg [NMATCH];
__device__ float g_iou [NMATCH];
__device__ float g_corr[NMATCH];

// ---------------------------------------------------------------------------
// Kernel 1: TMA bulk-copy staged cost. One cp.async.bulk per tile (contiguous
// 39936 B), mbarrier completion. 256 threads, 2 threads per row.
// grid (96, NTILE, 2).
// ---------------------------------------------------------------------------
__global__ __launch_bounds__(256, 5) void cost_kernel(
    const float* __restrict__ predA,
    const float* __restrict__ predB,
    const float* __restrict__ gt)
{
    const int sb     = blockIdx.x;
    const int tile   = blockIdx.y;
    const int branch = blockIdx.z;
    const int n0     = tile * TILE;
    const int T      = (n0 + TILE <= NPRIOR) ? TILE : (NPRIOR - n0);
    const float* __restrict__ pred = branch ? predB : predA;
    const int b = sb % BATCH;
    const char* gbase = (const char*)(pred + ((size_t)sb * NPRIOR + n0) * DFEAT);
    const size_t bs = (size_t)branch * SB + sb;

    __shared__ __align__(16) char  sh_buf[TILE * ROWB];   // 39936 B, linear
    __shared__ __align__(16) float sh_gt8[39][8];
    __shared__ float sh_geo[LANES][4];
    __shared__ float sh_acc[LANES][TILE];                 // half-1 partials -> costs
    __shared__ __align__(8) unsigned long long sh_mbar;

    const int tid  = threadIdx.x;
    const int warp = tid >> 5, lane = tid & 31;
    const unsigned FULL = 0xffffffffu;
    const unsigned sp   = (unsigned)__cvta_generic_to_shared(sh_buf);
    const unsigned mb   = (unsigned)__cvta_generic_to_shared(&sh_mbar);
    const unsigned tile_bytes = (unsigned)(T * ROWB);

    if (tid == 0)
        asm volatile("mbarrier.init.shared.b64 [%0], 1;" :: "r"(mb) : "memory");
    __syncthreads();

    if (tid == 0) {
        asm volatile("mbarrier.arrive.expect_tx.shared.b64 _, [%0], %1;"
                     :: "r"(mb), "r"(tile_bytes) : "memory");
        asm volatile("cp.async.bulk.shared::cta.global.mbarrier::complete_tx::bytes "
                     "[%0], [%1], %2, [%3];"
                     :: "r"(sp), "l"(gbase), "r"(tile_bytes), "r"(mb) : "memory");
    }

    // gt tables (overlap with bulk DMA)
    for (int i = tid; i < 39 * 8; i += 256) {
        int k = i >> 3, j = i & 7;
        int l = j >> 1, comp = j & 1;
        int d = 2 * k + comp;
        float v = 0.0f;
        if (d >= 6 && d < DFEAT)
            v = gt[((size_t)b * LANES + l) * DFEAT + d] * (1.0f / IMG_W1_F);
        sh_gt8[k][j] = v;
    }
    if (tid < 16)
        sh_geo[tid >> 2][tid & 3] =
            gt[((size_t)b * LANES + (tid >> 2)) * DFEAT + 2 + (tid & 3)];

    // wait for bulk copy (parity 0)
    {
        unsigned done;
        asm volatile(
            "{\n\t.reg .pred p;\n\t"
            "mbarrier.try_wait.parity.shared.b64 p, [%1], 0;\n\t"
            "selp.b32 %0, 1, 0, p;\n\t}"
            : "=r"(done) : "r"(mb) : "memory");
        while (!done) {
            asm volatile(
                "{\n\t.reg .pred p;\n\t"
                "mbarrier.try_wait.parity.shared.b64 p, [%1], 0, 0x989680;\n\t"
                "selp.b32 %0, 1, 0, p;\n\t}"
                : "=r"(done) : "r"(mb) : "memory");
        }
    }
    __syncthreads();

    // ---- compute: 2 threads per row (warps 0-3: half0, warps 4-7: half1)
    const int row  = tid & 127;
    const int half = tid >> 7;
    const char* rb = sh_buf + row * ROWB;

    float cg[LANES], o[LANES];
    float x0 = 0.0f, x1 = 0.0f;
    if (row < T) {
        if (half == 1) {
            float o2[LANES] = {0.0f, 0.0f, 0.0f, 0.0f};
            #pragma unroll
            for (int k = 21; k < 39; k++) {
                float2 pv = *(const float2*)(rb + k * 8);
                float4 ga = *(const float4*)&sh_gt8[k][0];
                float4 gb = *(const float4*)&sh_gt8[k][4];
                o2[0] += fabsf(pv.x - ga.x) + fabsf(pv.y - ga.y);
                o2[1] += fabsf(pv.x - ga.z) + fabsf(pv.y - ga.w);
                o2[2] += fabsf(pv.x - gb.x) + fabsf(pv.y - gb.y);
                o2[3] += fabsf(pv.x - gb.z) + fabsf(pv.y - gb.w);
            }
            #pragma unroll
            for (int l = 0; l < LANES; l++) sh_acc[l][row] = o2[l];
        } else {
            float2 q0 = *(const float2*)(rb);        // d0,d1 logits
            float2 q1 = *(const float2*)(rb + 8);    // d2,d3
            float2 q2 = *(const float2*)(rb + 16);   // d4,d5
            x0 = q0.x; x1 = q0.y;
            #pragma unroll
            for (int l = 0; l < LANES; l++) {
                cg[l] = fabsf(q1.x - sh_geo[l][0]) + fabsf(q1.y - sh_geo[l][1])
                      + fabsf(q2.x - sh_geo[l][2]) + fabsf(q2.y - sh_geo[l][3]);
                o[l] = 0.0f;
            }
            #pragma unroll
            for (int k = 3; k < 21; k++) {
                float2 pv = *(const float2*)(rb + k * 8);
                float4 ga = *(const float4*)&sh_gt8[k][0];
                float4 gb = *(const float4*)&sh_gt8[k][4];
                o[0] += fabsf(pv.x - ga.x) + fabsf(pv.y - ga.y);
                o[1] += fabsf(pv.x - ga.z) + fabsf(pv.y - ga.w);
                o[2] += fabsf(pv.x - gb.x) + fabsf(pv.y - gb.y);
                o[3] += fabsf(pv.x - gb.z) + fabsf(pv.y - gb.w);
            }
        }
    }
    __syncthreads();

    if (half == 0) {
        if (row < T) {
            float m  = fmaxf(x0, x1);
            float e0 = expf(x0 - m), e1 = expf(x1 - m);
            float denom = e0 + e1;
            float score = e1 / denom;
            // read half-1 partial, then overwrite SAME slot with final cost
            #pragma unroll
            for (int l = 0; l < LANES; l++) {
                float tot = o[l] + sh_acc[l][row];
                sh_acc[l][row] = cg[l] + tot * (1.0f / 72.0f) - score;
            }
            float lse = m + logf(denom);
            float om0 = 1.0f - e0 / denom;
            float cneg = -0.1f * om0 * om0 * (x0 - lse);
            atomicAdd(&g_cls_acc[branch * NPRIOR + n0 + row],
                      (unsigned long long)(long long)__float2ll_rn(cneg * FIXSCALE));
        } else {
            #pragma unroll
            for (int l = 0; l < LANES; l++) sh_acc[l][row] = INFINITY;
        }
    }
    __syncthreads();

    // ---- warps 0..3: top-4 of column w within tile, first-index tie-break
    if (warp < LANES) {
        const int w = warp;
        const size_t base = ((bs * LANES + w) * NTILE + tile) * 4;
        #pragma unroll
        for (int pass = 0; pass < 4; pass++) {
            float v = INFINITY; int li = INT_MAX;
            #pragma unroll
            for (int j0 = 0; j0 < TILE; j0 += 32) {
                int j = j0 + lane;
                float cc = sh_acc[w][j];
                if (cc < v || (cc == v && j < li)) { v = cc; li = j; }
            }
            #pragma unroll
            for (int off = 16; off; off >>= 1) {
                float v2 = __shfl_xor_sync(FULL, v, off);
                int   i2 = __shfl_xor_sync(FULL, li, off);
                if (v2 < v || (v2 == v && i2 < li)) { v = v2; li = i2; }
            }
            if (lane == 0) {
                g_cv[base + pass] = v;
                g_ci[base + pass] = n0 + li;
                sh_acc[w][li] = INFINITY;
            }
            __syncwarp(FULL);
        }
    }
}

// ---------------------------------------------------------------------------
// Kernel 2: per-task greedy merge + reg/iou/corr. grid 192, 128 threads.
// ---------------------------------------------------------------------------
__global__ __launch_bounds__(128) void match_kernel(
    const float* __restrict__ predA,
    const float* __restrict__ predB,
    const float* __restrict__ gt)
{
    const int task   = blockIdx.x;             // 0..191
    const int branch = task / SB;
    const int sb     = task % SB;
    const int b      = sb % BATCH;

    __shared__ int rows_sh[LANES];

    const int tid  = threadIdx.x;
    const int warp = tid >> 5, lane = tid & 31;
    const unsigned FULL = 0xffffffffu;

    if (warp == 0) {
        const size_t base = (size_t)task * LANES * NCAND;
        float cv[LANES][2]; int ci[LANES][2];
        #pragma unroll
        for (int col = 0; col < LANES; col++) {
            cv[col][0] = g_cv[base + col * NCAND + lane];
            cv[col][1] = g_cv[base + col * NCAND + 32 + lane];
            ci[col][0] = g_ci[base + col * NCAND + lane];
            ci[col][1] = g_ci[base + col * NCAND + 32 + lane];
        }
        int u0 = -1, u1 = -1, u2 = -1;
        #pragma unroll
        for (int col = 0; col < LANES; col++) {
            float v = INFINITY; int li = INT_MAX;
            #pragma unroll
            for (int k = 0; k < 2; k++) {
                int   i2 = ci[col][k];
                float v2 = cv[col][k];
                bool excl = (i2 == u0) | (i2 == u1) | (i2 == u2);
                if (!excl && (v2 < v || (v2 == v && i2 < li))) { v = v2; li = i2; }
            }
            #pragma unroll
            for (int off = 16; off; off >>= 1) {
                float v2 = __shfl_xor_sync(FULL, v, off);
                int   i2 = __shfl_xor_sync(FULL, li, off);
                if (v2 < v || (v2 == v && i2 < li)) { v = v2; li = i2; }
            }
            if (lane == 0) { rows_sh[col] = li; g_rows[task * LANES + col] = li; }
            if (col == 0) u0 = li; else if (col == 1) u1 = li; else if (col == 2) u2 = li;
        }
    }
    __syncthreads();

    {
        const int l = warp;
        const int r = rows_sh[l];
        const int mm = task * LANES + l;
        const float* p  = (branch ? predB : predA)
                          + ((size_t)sb * NPRIOR + r) * DFEAT;
        const float* tg = gt + ((size_t)b * LANES + l) * DFEAT;

        float ovrS = 0.0f, uniS = 0.0f;
        #pragma unroll
        for (int kb = 0; kb < 3; kb++) {
            int k = kb * 32 + lane;
            if (k < NOFF) {
                float rp = p[6 + k] * IMG_W1_F;
                float rt = tg[6 + k];
                bool invalid = (rt < 0.0f) || (rt >= IMG_W_F);
                float mn = fminf(rp, rt), mx = fmaxf(rp, rt);
                if (!invalid) {
                    ovrS += (mn - mx + 30.0f);
                    uniS += (mx - mn + 30.0f);
                }
            }
        }
        #pragma unroll
        for (int off = 16; off; off >>= 1) {
            ovrS += __shfl_xor_sync(FULL, ovrS, off);
            uniS += __shfl_xor_sync(FULL, uniS, off);
        }
        if (lane == 0) {
            float iou = ovrS / (uniS + 1e-9f);
            g_iou[mm] = (1.0f - iou) * 0.25f;
            const float sc[4] = {71.0f, IMG_W1_F, 180.0f, 71.0f};
            float ssum = 0.0f;
            #pragma unroll
            for (int j = 0; j < 4; j++) {
                float d  = (p[2 + j] - tg[2 + j]) * sc[j];
                float ad = fabsf(d);
                ssum += (ad < 1.0f) ? 0.5f * d * d : ad - 0.5f;
            }
            g_reg[mm] = ssum * 0.0625f;   // mean over 4, /L

            float x0 = p[0], x1 = p[1];
            float m2  = fmaxf(x0, x1);
            float e0 = expf(x0 - m2), e1 = expf(x1 - m2);
            float denom = e0 + e1;
            float lse = m2 + logf(denom);
            float om0 = 1.0f - e0 / denom, om1 = 1.0f - e1 / denom;
            float cneg = -0.1f * om0 * om0 * (x0 - lse);
            float cpos = -0.9f * om1 * om1 * (x1 - lse);
            g_corr[mm] = (cpos - cneg) * (2.0f / 96.0f);
        }
    }
}

// ---------------------------------------------------------------------------
// Kernel 3: inst build + corrections + dual-rank radix median + weighted sum.
// Single block, 1024 threads.
// ---------------------------------------------------------------------------
__global__ __launch_bounds__(1024) void final_kernel(
    const float* __restrict__ diff,
    float* __restrict__ out)
{
    __shared__ float instA[NPRIOR];
    __shared__ float instB[NPRIOR];
    __shared__ unsigned ukey[NPRIOR];
    __shared__ int   hist[2][256];
    __shared__ float red[1024];
    __shared__ int   s_bin[2], s_k[2];

    const int tid = threadIdx.x;
    const int warp = tid >> 5, lane = tid & 31;
    const unsigned FULL = 0xffffffffu;

    const float CLS_K = (float)(2.0 / 96.0 / 1099511627776.0);
    for (int n = tid; n < NPRIOR; n += 1024) {
        long long a0 = (long long)g_cls_acc[n];
        long long b0 = (long long)g_cls_acc[NPRIOR + n];
        instA[n] = (float)a0 * CLS_K;
        instB[n] = (float)b0 * CLS_K;
        g_cls_acc[n] = 0ull;
        g_cls_acc[NPRIOR + n] = 0ull;
    }
    __syncthreads();

    if (tid < NMATCH) {
        const int branch = tid / (SB * LANES);
        const int r = g_rows[tid];
        atomicAdd(branch == 0 ? &instA[r] : &instB[r], g_corr[tid]);
    }
    if (tid >= 1016) {
        const int t = tid - 1016;
        const int branch = t >> 2, l = t & 3;
        float rs = 0.0f, is = 0.0f;
        #pragma unroll 8
        for (int i = 0; i < SB; i++) {
            rs += g_reg[(branch * SB + i) * LANES + l];
            is += g_iou[(branch * SB + i) * LANES + l];
        }
        float add = rs * (0.5f / 96.0f) + is * (2.0f / 96.0f);
        int r = g_rows[(branch * SB + (SB - 1)) * LANES + l];
        atomicAdd(branch == 0 ? &instA[r] : &instB[r], add);
    }
    __syncthreads();

    for (int n = tid; n < NPRIOR; n += 1024) {
        float f = instA[n] - instB[n];
        unsigned x = __float_as_uint(f);
        ukey[n] = (x & 0x80000000u) ? ~x : (x | 0x80000000u);
    }
    __syncthreads();

    unsigned prefix[2] = {0u, 0u};
    unsigned mask = 0u;
    int kk[2] = {999, 1000};
    for (int shift = 24; shift >= 0; shift -= 8) {
        if (tid < 512) hist[tid >> 8][tid & 255] = 0;
        __syncthreads();
        for (int n = tid; n < NPRIOR; n += 1024) {
            unsigned u = ukey[n];
            unsigned bin = (u >> shift) & 255u;
            unsigned hi = u & mask;
            if (hi == prefix[0]) atomicAdd(&hist[0][bin], 1);
            if (hi == prefix[1]) atomicAdd(&hist[1][bin], 1);
        }
        __syncthreads();
        if (tid < 64) {
            const int trk = warp;
            int kt = kk[trk];
            int cnt[8]; int local = 0;
            #pragma unroll
            for (int k2 = 0; k2 < 8; k2++) { cnt[k2] = hist[trk][lane * 8 + k2]; local += cnt[k2]; }
            int pre = local;
            #pragma unroll
            for (int off = 1; off < 32; off <<= 1) {
                int t2 = __shfl_up_sync(FULL, pre, off);
                if (lane >= off) pre += t2;
            }
            int run = pre - local;
            int foundk = -1, myrun = 0;
            #pragma unroll
            for (int k2 = 0; k2 < 8; k2++) {
                if (foundk < 0 && kt >= run && kt < run + cnt[k2]) { foundk = k2; myrun = run; }
                run += cnt[k2];
            }
            unsigned bm = __ballot_sync(FULL, foundk >= 0);
            int src = __ffs(bm) - 1;
            if (lane == src) { s_bin[trk] = lane * 8 + foundk; s_k[trk] = kt - myrun; }
        }
        __syncthreads();
        prefix[0] |= ((unsigned)s_bin[0]) << shift;
        prefix[1] |= ((unsigned)s_bin[1]) << shift;
        mask |= 0xFFu << shift;
        kk[0] = s_k[0]; kk[1] = s_k[1];
        __syncthreads();
    }
    float m0 = (prefix[0] & 0x80000000u) ? __uint_as_float(prefix[0] ^ 0x80000000u)
                                         : __uint_as_float(~prefix[0]);
    float m1 = (prefix[1] & 0x80000000u) ? __uint_as_float(prefix[1] ^ 0x80000000u)
                                         : __uint_as_float(~prefix[1]);
    float delta = 0.5f * (m0 + m1);

    float acc = 0.0f;
    for (int n = tid; n < NPRIOR; n += 1024) {
        float dm = (diff[n] + diff[NPRIOR + n] + diff[2 * NPRIOR + n]) * (1.0f / 3.0f);
        acc += (1.0f - dm) * (instA[n] - 0.5f * delta)
             + dm          * (instB[n] + 0.5f * delta);
    }
    red[tid] = acc;
    __syncthreads();
    for (int off = 512; off; off >>= 1) {
        if (tid < off) red[tid] += red[tid + off];
        __syncthreads();
    }
    if (tid == 0) out[0] = red[0];
}

// ---------------------------------------------------------------------------
extern "C" void kernel_launch(void* const* d_in, const int* in_sizes, int n_in,
                              void* d_out, int out_size)
{
    const float* fir  = (const float*)d_in[0];
    const float* sec  = (const float*)d_in[1];
    const float* gt   = (const float*)d_in[2];
    const float* diff = (const float*)d_in[3];
    float* out = (float*)d_out;

    cost_kernel <<<dim3(SB, NTILE, 2), 256>>>(fir, sec, gt);
    match_kernel<<<NTASK, 128>>>(fir, sec, gt);
    final_kernel<<<1, 1024>>>(diff, out);
}

// round 14
// speedup vs baseline: 1.4505x; 1.1207x over previous
#include <cuda_runtime.h>
#include <math.h>
#include <limits.h>

#define S_STAGES 3
#define BATCH    32
#define NPRIOR   2000
#define LANES    4
#define DFEAT    78          // 2 + 4 + 72
#define NOFF     72
#define SB       96
#define IMG_W_F  800.0f
#define IMG_W1_F 799.0f
#define TILE     128
#define NTILE    16          // 15 full tiles + one of 80
#define ROWB     312         // bytes per row
#define NCAND    (NTILE * 4) // 64 candidates per column
#define NMATCH   (2 * SB * LANES)   // 768
#define NTASK    (2 * SB)           // 192
#define FIXSCALE 1099511627776.0f   // 2^40

// Scratch (device globals — no allocation allowed)
// g_cls_acc is zero at load; final_kernel re-zeroes after consuming (replay-safe).
__device__ unsigned long long g_cls_acc[2 * NPRIOR];
__device__ float g_cv[NTASK * LANES * NCAND];
__device__ int   g_ci[NTASK * LANES * NCAND];
__device__ int   g_rows[NMATCH];
__device__ float g_reg [NMATCH];
__device__ float g_iou [NMATCH];
__device__ float g_corr[NMATCH];

// ---------------------------------------------------------------------------
// Kernel 1: TMA bulk-copy staged cost. One cp.async.bulk per tile (contiguous
// 39936 B), mbarrier completion. 256 threads, 2 threads per row.
// grid (96, NTILE, 2).
// ---------------------------------------------------------------------------
__global__ __launch_bounds__(256, 5) void cost_kernel(
    const float* __restrict__ predA,
    const float* __restrict__ predB,
    const float* __restrict__ gt)
{
    const int sb     = blockIdx.x;
    const int tile   = blockIdx.y;
    const int branch = blockIdx.z;
    const int n0     = tile * TILE;
    const int T      = (n0 + TILE <= NPRIOR) ? TILE : (NPRIOR - n0);
    const float* __restrict__ pred = branch ? predB : predA;
    const int b = sb % BATCH;
    const char* gbase = (const char*)(pred + ((size_t)sb * NPRIOR + n0) * DFEAT);
    const size_t bs = (size_t)branch * SB + sb;

    __shared__ __align__(16) char  sh_buf[TILE * ROWB];   // 39936 B, linear
    __shared__ __align__(16) float sh_gt8[39][8];
    __shared__ float sh_geo[LANES][4];
    __shared__ float sh_acc[LANES][TILE];                 // half-1 partials -> costs
    __shared__ __align__(8) unsigned long long sh_mbar;

    const int tid  = threadIdx.x;
    const int warp = tid >> 5, lane = tid & 31;
    const unsigned FULL = 0xffffffffu;
    const unsigned sp   = (unsigned)__cvta_generic_to_shared(sh_buf);
    const unsigned mb   = (unsigned)__cvta_generic_to_shared(&sh_mbar);
    const unsigned tile_bytes = (unsigned)(T * ROWB);

    if (tid == 0)
        asm volatile("mbarrier.init.shared.b64 [%0], 1;" :: "r"(mb) : "memory");
    __syncthreads();

    if (tid == 0) {
        asm volatile("mbarrier.arrive.expect_tx.shared.b64 _, [%0], %1;"
                     :: "r"(mb), "r"(tile_bytes) : "memory");
        asm volatile("cp.async.bulk.shared::cta.global.mbarrier::complete_tx::bytes "
                     "[%0], [%1], %2, [%3];"
                     :: "r"(sp), "l"(gbase), "r"(tile_bytes), "r"(mb) : "memory");
    }

    // gt tables (overlap with bulk DMA)
    for (int i = tid; i < 39 * 8; i += 256) {
        int k = i >> 3, j = i & 7;
        int l = j >> 1, comp = j & 1;
        int d = 2 * k + comp;
        float v = 0.0f;
        if (d >= 6 && d < DFEAT)
            v = gt[((size_t)b * LANES + l) * DFEAT + d] * (1.0f / IMG_W1_F);
        sh_gt8[k][j] = v;
    }
    if (tid < 16)
        sh_geo[tid >> 2][tid & 3] =
            gt[((size_t)b * LANES + (tid >> 2)) * DFEAT + 2 + (tid & 3)];

    // wait for bulk copy (parity 0)
    {
        unsigned done;
        asm volatile(
            "{\n\t.reg .pred p;\n\t"
            "mbarrier.try_wait.parity.shared.b64 p, [%1], 0;\n\t"
            "selp.b32 %0, 1, 0, p;\n\t}"
            : "=r"(done) : "r"(mb) : "memory");
        while (!done) {
            asm volatile(
                "{\n\t.reg .pred p;\n\t"
                "mbarrier.try_wait.parity.shared.b64 p, [%1], 0, 0x989680;\n\t"
                "selp.b32 %0, 1, 0, p;\n\t}"
                : "=r"(done) : "r"(mb) : "memory");
        }
    }
    __syncthreads();

    // ---- compute: 2 threads per row (warps 0-3: half0, warps 4-7: half1)
    const int row  = tid & 127;
    const int half = tid >> 7;
    const char* rb = sh_buf + row * ROWB;

    float cg[LANES], o[LANES];
    float x0 = 0.0f, x1 = 0.0f;
    if (row < T) {
        if (half == 1) {
            float o2[LANES] = {0.0f, 0.0f, 0.0f, 0.0f};
            #pragma unroll
            for (int k = 21; k < 39; k++) {
                float2 pv = *(const float2*)(rb + k * 8);
                float4 ga = *(const float4*)&sh_gt8[k][0];
                float4 gb = *(const float4*)&sh_gt8[k][4];
                o2[0] += fabsf(pv.x - ga.x) + fabsf(pv.y - ga.y);
                o2[1] += fabsf(pv.x - ga.z) + fabsf(pv.y - ga.w);
                o2[2] += fabsf(pv.x - gb.x) + fabsf(pv.y - gb.y);
                o2[3] += fabsf(pv.x - gb.z) + fabsf(pv.y - gb.w);
            }
            #pragma unroll
            for (int l = 0; l < LANES; l++) sh_acc[l][row] = o2[l];
        } else {
            float2 q0 = *(const float2*)(rb);        // d0,d1 logits
            float2 q1 = *(const float2*)(rb + 8);    // d2,d3
            float2 q2 = *(const float2*)(rb + 16);   // d4,d5
            x0 = q0.x; x1 = q0.y;
            #pragma unroll
            for (int l = 0; l < LANES; l++) {
                cg[l] = fabsf(q1.x - sh_geo[l][0]) + fabsf(q1.y - sh_geo[l][1])
                      + fabsf(q2.x - sh_geo[l][2]) + fabsf(q2.y - sh_geo[l][3]);
                o[l] = 0.0f;
            }
            #pragma unroll
            for (int k = 3; k < 21; k++) {
                float2 pv = *(const float2*)(rb + k * 8);
                float4 ga = *(const float4*)&sh_gt8[k][0];
                float4 gb = *(const float4*)&sh_gt8[k][4];
                o[0] += fabsf(pv.x - ga.x) + fabsf(pv.y - ga.y);
                o[1] += fabsf(pv.x - ga.z) + fabsf(pv.y - ga.w);
                o[2] += fabsf(pv.x - gb.x) + fabsf(pv.y - gb.y);
                o[3] += fabsf(pv.x - gb.z) + fabsf(pv.y - gb.w);
            }
        }
    }
    __syncthreads();

    if (half == 0) {
        if (row < T) {
            float m  = fmaxf(x0, x1);
            float e0 = expf(x0 - m), e1 = expf(x1 - m);
            float denom = e0 + e1;
            float score = e1 / denom;
            // read half-1 partial, then overwrite SAME slot with final cost
            #pragma unroll
            for (int l = 0; l < LANES; l++) {
                float tot = o[l] + sh_acc[l][row];
                sh_acc[l][row] = cg[l] + tot * (1.0f / 72.0f) - score;
            }
            float lse = m + logf(denom);
            float om0 = 1.0f - e0 / denom;
            float cneg = -0.1f * om0 * om0 * (x0 - lse);
            atomicAdd(&g_cls_acc[branch * NPRIOR + n0 + row],
                      (unsigned long long)(long long)__float2ll_rn(cneg * FIXSCALE));
        } else {
            #pragma unroll
            for (int l = 0; l < LANES; l++) sh_acc[l][row] = INFINITY;
        }
    }
    __syncthreads();

    // ---- warps 0..3: top-4 of column w within tile, first-index tie-break
    if (warp < LANES) {
        const int w = warp;
        const size_t base = ((bs * LANES + w) * NTILE + tile) * 4;
        #pragma unroll
        for (int pass = 0; pass < 4; pass++) {
            float v = INFINITY; int li = INT_MAX;
            #pragma unroll
            for (int j0 = 0; j0 < TILE; j0 += 32) {
                int j = j0 + lane;
                float cc = sh_acc[w][j];
                if (cc < v || (cc == v && j < li)) { v = cc; li = j; }
            }
            #pragma unroll
            for (int off = 16; off; off >>= 1) {
                float v2 = __shfl_xor_sync(FULL, v, off);
                int   i2 = __shfl_xor_sync(FULL, li, off);
                if (v2 < v || (v2 == v && i2 < li)) { v = v2; li = i2; }
            }
            if (lane == 0) {
                g_cv[base + pass] = v;
                g_ci[base + pass] = n0 + li;
                sh_acc[w][li] = INFINITY;
            }
            __syncwarp(FULL);
        }
    }
}

// ---------------------------------------------------------------------------
// Kernel 2: per-task greedy merge + reg/iou/corr. grid 192, 128 threads.
// ---------------------------------------------------------------------------
__global__ __launch_bounds__(128) void match_kernel(
    const float* __restrict__ predA,
    const float* __restrict__ predB,
    const float* __restrict__ gt)
{
    const int task   = blockIdx.x;             // 0..191
    const int branch = task / SB;
    const int sb     = task % SB;
    const int b      = sb % BATCH;

    __shared__ int rows_sh[LANES];

    const int tid  = threadIdx.x;
    const int warp = tid >> 5, lane = tid & 31;
    const unsigned FULL = 0xffffffffu;

    if (warp == 0) {
        const size_t base = (size_t)task * LANES * NCAND;
        float cv[LANES][2]; int ci[LANES][2];
        #pragma unroll
        for (int col = 0; col < LANES; col++) {
            cv[col][0] = g_cv[base + col * NCAND + lane];
            cv[col][1] = g_cv[base + col * NCAND + 32 + lane];
            ci[col][0] = g_ci[base + col * NCAND + lane];
            ci[col][1] = g_ci[base + col * NCAND + 32 + lane];
        }
        int u0 = -1, u1 = -1, u2 = -1;
        #pragma unroll
        for (int col = 0; col < LANES; col++) {
            float v = INFINITY; int li = INT_MAX;
            #pragma unroll
            for (int k = 0; k < 2; k++) {
                int   i2 = ci[col][k];
                float v2 = cv[col][k];
                bool excl = (i2 == u0) | (i2 == u1) | (i2 == u2);
                if (!excl && (v2 < v || (v2 == v && i2 < li))) { v = v2; li = i2; }
            }
            #pragma unroll
            for (int off = 16; off; off >>= 1) {
                float v2 = __shfl_xor_sync(FULL, v, off);
                int   i2 = __shfl_xor_sync(FULL, li, off);
                if (v2 < v || (v2 == v && i2 < li)) { v = v2; li = i2; }
            }
            if (lane == 0) { rows_sh[col] = li; g_rows[task * LANES + col] = li; }
            if (col == 0) u0 = li; else if (col == 1) u1 = li; else if (col == 2) u2 = li;
        }
    }
    __syncthreads();

    {
        const int l = warp;
        const int r = rows_sh[l];
        const int mm = task * LANES + l;
        const float* p  = (branch ? predB : predA)
                          + ((size_t)sb * NPRIOR + r) * DFEAT;
        const float* tg = gt + ((size_t)b * LANES + l) * DFEAT;

        float ovrS = 0.0f, uniS = 0.0f;
        #pragma unroll
        for (int kb = 0; kb < 3; kb++) {
            int k = kb * 32 + lane;
            if (k < NOFF) {
                float rp = p[6 + k] * IMG_W1_F;
                float rt = tg[6 + k];
                bool invalid = (rt < 0.0f) || (rt >= IMG_W_F);
                float mn = fminf(rp, rt), mx = fmaxf(rp, rt);
                if (!invalid) {
                    ovrS += (mn - mx + 30.0f);
                    uniS += (mx - mn + 30.0f);
                }
            }
        }
        #pragma unroll
        for (int off = 16; off; off >>= 1) {
            ovrS += __shfl_xor_sync(FULL, ovrS, off);
            uniS += __shfl_xor_sync(FULL, uniS, off);
        }
        if (lane == 0) {
            float iou = ovrS / (uniS + 1e-9f);
            g_iou[mm] = (1.0f - iou) * 0.25f;
            const float sc[4] = {71.0f, IMG_W1_F, 180.0f, 71.0f};
            float ssum = 0.0f;
            #pragma unroll
            for (int j = 0; j < 4; j++) {
                float d  = (p[2 + j] - tg[2 + j]) * sc[j];
                float ad = fabsf(d);
                ssum += (ad < 1.0f) ? 0.5f * d * d : ad - 0.5f;
            }
            g_reg[mm] = ssum * 0.0625f;   // mean over 4, /L

            float x0 = p[0], x1 = p[1];
            float m2  = fmaxf(x0, x1);
            float e0 = expf(x0 - m2), e1 = expf(x1 - m2);
            float denom = e0 + e1;
            float lse = m2 + logf(denom);
            float om0 = 1.0f - e0 / denom, om1 = 1.0f - e1 / denom;
            float cneg = -0.1f * om0 * om0 * (x0 - lse);
            float cpos = -0.9f * om1 * om1 * (x1 - lse);
            g_corr[mm] = (cpos - cneg) * (2.0f / 96.0f);
        }
    }
}

// ---------------------------------------------------------------------------
// Kernel 3: inst build + corrections + dual-rank radix median + weighted sum.
// Single block, 1024 threads. reg/iou staged through SMEM (no serial global
// latency chains).
// ---------------------------------------------------------------------------
__global__ __launch_bounds__(1024) void final_kernel(
    const float* __restrict__ diff,
    float* __restrict__ out)
{
    __shared__ float instA[NPRIOR];
    __shared__ float instB[NPRIOR];
    __shared__ unsigned ukey[NPRIOR];
    __shared__ float reg_sh[NMATCH];
    __shared__ float iou_sh[NMATCH];
    __shared__ int   hist[2][256];
    __shared__ float red[1024];
    __shared__ int   s_bin[2], s_k[2];

    const int tid = threadIdx.x;
    const int warp = tid >> 5, lane = tid & 31;
    const unsigned FULL = 0xffffffffu;

    // cooperative parallel loads: cls accumulators + reg/iou into SMEM
    const float CLS_K = (float)(2.0 / 96.0 / 1099511627776.0);
    for (int n = tid; n < NPRIOR; n += 1024) {
        long long a0 = (long long)g_cls_acc[n];
        long long b0 = (long long)g_cls_acc[NPRIOR + n];
        instA[n] = (float)a0 * CLS_K;
        instB[n] = (float)b0 * CLS_K;
        g_cls_acc[n] = 0ull;
        g_cls_acc[NPRIOR + n] = 0ull;
    }
    if (tid < NMATCH) {
        reg_sh[tid] = g_reg[tid];
        iou_sh[tid] = g_iou[tid];
    }
    __syncthreads();

    // matched-row focal corrections (parallel, 768 threads)
    if (tid < NMATCH) {
        const int branch = tid / (SB * LANES);
        const int r = g_rows[tid];
        atomicAdd(branch == 0 ? &instA[r] : &instB[r], g_corr[tid]);
    }
    // reg/iou sums from SMEM: 64 threads, 8 lanes per (branch,l) group
    if (tid >= 960 && tid < 1024) {
        const int t = tid - 960;
        const int g = t >> 3;              // 0..7 = branch*4 + l
        const int j = t & 7;
        const int branch = g >> 2, l = g & 3;
        float rs = 0.0f, is = 0.0f;
        #pragma unroll
        for (int i = j; i < SB; i += 8) {
            rs += reg_sh[(branch * SB + i) * LANES + l];
            is += iou_sh[(branch * SB + i) * LANES + l];
        }
        // reduce within each 8-lane group (tid 960..1023 = warps 30,31 fully active)
        #pragma unroll
        for (int off = 4; off; off >>= 1) {
            rs += __shfl_down_sync(FULL, rs, off, 8);
            is += __shfl_down_sync(FULL, is, off, 8);
        }
        if (j == 0) {
            float add = rs * (0.5f / 96.0f) + is * (2.0f / 96.0f);
            int r = g_rows[(branch * SB + (SB - 1)) * LANES + l];
            atomicAdd(branch == 0 ? &instA[r] : &instB[r], add);
        }
    }
    __syncthreads();

    // median via dual-rank radix select
    for (int n = tid; n < NPRIOR; n += 1024) {
        float f = instA[n] - instB[n];
        unsigned x = __float_as_uint(f);
        ukey[n] = (x & 0x80000000u) ? ~x : (x | 0x80000000u);
    }
    __syncthreads();

    unsigned prefix[2] = {0u, 0u};
    unsigned mask = 0u;
    int kk[2] = {999, 1000};
    for (int shift = 24; shift >= 0; shift -= 8) {
        if (tid < 512) hist[tid >> 8][tid & 255] = 0;
        __syncthreads();
        for (int n = tid; n < NPRIOR; n += 1024) {
            unsigned u = ukey[n];
            unsigned bin = (u >> shift) & 255u;
            unsigned hi = u & mask;
            if (hi == prefix[0]) atomicAdd(&hist[0][bin], 1);
            if (hi == prefix[1]) atomicAdd(&hist[1][bin], 1);
        }
        __syncthreads();
        if (tid < 64) {
            const int trk = warp;
            int kt = kk[trk];
            int cnt[8]; int local = 0;
            #pragma unroll
            for (int k2 = 0; k2 < 8; k2++) { cnt[k2] = hist[trk][lane * 8 + k2]; local += cnt[k2]; }
            int pre = local;
            #pragma unroll
            for (int off = 1; off < 32; off <<= 1) {
                int t2 = __shfl_up_sync(FULL, pre, off);
                if (lane >= off) pre += t2;
            }
            int run = pre - local;
            int foundk = -1, myrun = 0;
            #pragma unroll
            for (int k2 = 0; k2 < 8; k2++) {
                if (foundk < 0 && kt >= run && kt < run + cnt[k2]) { foundk = k2; myrun = run; }
                run += cnt[k2];
            }
            unsigned bm = __ballot_sync(FULL, foundk >= 0);
            int src = __ffs(bm) - 1;
            if (lane == src) { s_bin[trk] = lane * 8 + foundk; s_k[trk] = kt - myrun; }
        }
        __syncthreads();
        prefix[0] |= ((unsigned)s_bin[0]) << shift;
        prefix[1] |= ((unsigned)s_bin[1]) << shift;
        mask |= 0xFFu << shift;
        kk[0] = s_k[0]; kk[1] = s_k[1];
        __syncthreads();
    }
    float m0 = (prefix[0] & 0x80000000u) ? __uint_as_float(prefix[0] ^ 0x80000000u)
                                         : __uint_as_float(~prefix[0]);
    float m1 = (prefix[1] & 0x80000000u) ? __uint_as_float(prefix[1] ^ 0x80000000u)
                                         : __uint_as_float(~prefix[1]);
    float delta = 0.5f * (m0 + m1);

    // final weighted sum
    float acc = 0.0f;
    for (int n = tid; n < NPRIOR; n += 1024) {
        float dm = (diff[n] + diff[NPRIOR + n] + diff[2 * NPRIOR + n]) * (1.0f / 3.0f);
        acc += (1.0f - dm) * (instA[n] - 0.5f * delta)
             + dm          * (instB[n] + 0.5f * delta);
    }
    red[tid] = acc;
    __syncthreads();
    for (int off = 512; off; off >>= 1) {
        if (tid < off) red[tid] += red[tid + off];
        __syncthreads();
    }
    if (tid == 0) out[0] = red[0];
}

// ---------------------------------------------------------------------------
extern "C" void kernel_launch(void* const* d_in, const int* in_sizes, int n_in,
                              void* d_out, int out_size)
{
    const float* fir  = (const float*)d_in[0];
    const float* sec  = (const float*)d_in[1];
    const float* gt   = (const float*)d_in[2];
    const float* diff = (const float*)d_in[3];
    float* out = (float*)d_out;

    cost_kernel <<<dim3(SB, NTILE, 2), 256>>>(fir, sec, gt);
    match_kernel<<<NTASK, 128>>>(fir, sec, gt);
    final_kernel<<<1, 1024>>>(diff, out);
}